// round 3
// baseline (speedup 1.0000x reference)
#include <cuda_runtime.h>

#define NPTS 500000
#define NVOX 65536

// Scratch (allocation-free rule: __device__ globals). 16B-aligned for float4 access.
static __device__ __align__(16) float g_pf2 [(size_t)NPTS * 128]; // point_feat2
static __device__ __align__(16) float g_vox1[(size_t)NVOX * 128]; // segment max 1
static __device__ __align__(16) float g_vox1g[(size_t)NVOX * 128]; // relu(vox1@Wv1+bv1)
static __device__ __align__(16) float g_pf4 [(size_t)NPTS * 256]; // point_feat4
static __device__ __align__(16) float g_vox2[(size_t)NVOX * 256]; // segment max 2

union f2u { float2 f; unsigned long long u; };

__device__ __forceinline__ void ffma2(f2u& d, const f2u& a, const f2u& b) {
    asm("fma.rn.f32x2 %0, %1, %2, %0;" : "+l"(d.u) : "l"(a.u), "l"(b.u));
}

// ---------------------------------------------------------------------------
// Zero-init the two segment-max accumulators (re-run every graph replay).
// ---------------------------------------------------------------------------
__global__ void k_zero() {
    const size_t n4a = (size_t)NVOX * 128 / 4;   // vox1 in float4
    const size_t n4b = (size_t)NVOX * 256 / 4;   // vox2 in float4
    float4 z = make_float4(0.f, 0.f, 0.f, 0.f);
    size_t stride = (size_t)gridDim.x * blockDim.x;
    for (size_t j = (size_t)blockIdx.x * blockDim.x + threadIdx.x; j < n4a + n4b; j += stride) {
        if (j < n4a) ((float4*)g_vox1)[j] = z;
        else         ((float4*)g_vox2)[j - n4a] = z;
    }
}

// ---------------------------------------------------------------------------
// K1: per-point MLP 6 -> 64 -> 128, store pf2, atomicMax into vox1.
// Weights staged in shared memory; one thread per point.
// ---------------------------------------------------------------------------
__global__ __launch_bounds__(256) void k1_pointwise(
    const float* __restrict__ inp, const int* __restrict__ idx,
    const float* __restrict__ W1, const float* __restrict__ b1,
    const float* __restrict__ W2, const float* __restrict__ b2)
{
    __shared__ __align__(16) float sW1[6 * 64];
    __shared__ __align__(16) float sb1[64];
    __shared__ __align__(16) float sW2[64 * 128];
    __shared__ __align__(16) float sb2[128];
    int t = threadIdx.x;
    for (int i = t; i < 6 * 64; i += 256) sW1[i] = W1[i];
    if (t < 64)  sb1[t] = b1[t];
    for (int i = t; i < 64 * 128; i += 256) sW2[i] = W2[i];
    if (t < 128) sb2[t] = b2[t];
    __syncthreads();

    int i = blockIdx.x * 256 + t;
    if (i >= NPTS) return;

    float x[6];
#pragma unroll
    for (int c = 0; c < 6; c++) x[c] = inp[(size_t)i * 6 + c];

    float pf1[64];
#pragma unroll
    for (int j = 0; j < 64; j++) {
        float a = sb1[j];
#pragma unroll
        for (int c = 0; c < 6; c++) a = fmaf(x[c], sW1[c * 64 + j], a);
        pf1[j] = fmaxf(a, 0.f);
    }

    int v = idx[i];
    float4* outrow = (float4*)(g_pf2 + (size_t)i * 128);
    int*    voxrow = (int*)(g_vox1 + (size_t)v * 128);
    const float4* sW2v = (const float4*)sW2;
    const float4* sb2v = (const float4*)sb2;

#pragma unroll 1
    for (int j4 = 0; j4 < 32; j4++) {
        float4 acc = sb2v[j4];
#pragma unroll
        for (int k = 0; k < 64; k++) {
            float4 w = sW2v[k * 32 + j4];
            float p = pf1[k];
            acc.x = fmaf(p, w.x, acc.x);
            acc.y = fmaf(p, w.y, acc.y);
            acc.z = fmaf(p, w.z, acc.z);
            acc.w = fmaf(p, w.w, acc.w);
        }
        acc.x = fmaxf(acc.x, 0.f); acc.y = fmaxf(acc.y, 0.f);
        acc.z = fmaxf(acc.z, 0.f); acc.w = fmaxf(acc.w, 0.f);
        outrow[j4] = acc;
        // values are >= 0 -> int-compare == float-compare
        atomicMax(voxrow + j4 * 4 + 0, __float_as_int(acc.x));
        atomicMax(voxrow + j4 * 4 + 1, __float_as_int(acc.y));
        atomicMax(voxrow + j4 * 4 + 2, __float_as_int(acc.z));
        atomicMax(voxrow + j4 * 4 + 3, __float_as_int(acc.w));
    }
}

// ---------------------------------------------------------------------------
// Generic fused GEMM: C = relu(A @ W + bias)
//   MODEA 0: A is a dense [M,K] row-major buffer.
//   MODEA 1: A[i, j] = j<128 ? G[idx[i]*128 + j] : P[i*128 + (j-128)]  (gather+concat)
//   MODEE 0: store C[M,Ncol]
//   MODEE 1: atomicMax-scatter rows into C[idx[i]*256 + n] (segment max)
// Tile 128x128x16, 256 threads, 8x8 microtile, packed f32x2 FMA.
// ---------------------------------------------------------------------------
template <int MODEA, int MODEE>
__global__ __launch_bounds__(256, 2) void k_gemm(
    const float* __restrict__ A,
    const float* __restrict__ G,
    const float* __restrict__ P,
    const int* __restrict__ idx,
    const float* __restrict__ W,
    const float* __restrict__ bias,
    float* __restrict__ C,
    int M, int K, int Ncol)
{
    __shared__ __align__(16) float As[16][128];
    __shared__ __align__(16) float Bs[16][128];

    int t  = threadIdx.x;
    int m0 = blockIdx.x * 128;
    int n0 = blockIdx.y * 128;
    int tm = t >> 4;     // 0..15 -> row group
    int tn = t & 15;     // 0..15 -> col group

    f2u acc[8][4];
#pragma unroll
    for (int m = 0; m < 8; m++)
#pragma unroll
        for (int p = 0; p < 4; p++) acc[m][p].u = 0ull;

    for (int k0 = 0; k0 < K; k0 += 16) {
#pragma unroll
        for (int q = 0; q < 2; q++) {
            int l = t * 2 + q;               // 0..511
            // ---- A tile: 128 rows x 16 cols ----
            int row  = l >> 2;               // 0..127
            int kseg = l & 3;                // 0..3 (float4 within k)
            int gr = m0 + row;
            int gk = k0 + kseg * 4;
            float4 va = make_float4(0.f, 0.f, 0.f, 0.f);
            if (gr < M) {
                const float* src;
                if (MODEA == 0) {
                    src = A + (size_t)gr * K + gk;
                } else {
                    if (gk < 128) src = G + (size_t)idx[gr] * 128 + gk;
                    else          src = P + (size_t)gr * 128 + (gk - 128);
                }
                va = *(const float4*)src;
            }
            As[kseg * 4 + 0][row] = va.x;
            As[kseg * 4 + 1][row] = va.y;
            As[kseg * 4 + 2][row] = va.z;
            As[kseg * 4 + 3][row] = va.w;
            // ---- B tile: 16 rows x 128 cols ----
            int rowb = l >> 5;               // 0..15
            int col4 = l & 31;               // 0..31
            float4 vb = *(const float4*)(W + (size_t)(k0 + rowb) * Ncol + n0 + col4 * 4);
            *(float4*)&Bs[rowb][col4 * 4] = vb;
        }
        __syncthreads();

#pragma unroll 4
        for (int kk = 0; kk < 16; kk++) {
            float4 a0 = *(const float4*)&As[kk][tm * 8];
            float4 a1 = *(const float4*)&As[kk][tm * 8 + 4];
            f2u b[4];
            const f2u* bp = (const f2u*)&Bs[kk][tn * 8];
            b[0] = bp[0]; b[1] = bp[1]; b[2] = bp[2]; b[3] = bp[3];
            float am[8] = {a0.x, a0.y, a0.z, a0.w, a1.x, a1.y, a1.z, a1.w};
#pragma unroll
            for (int m = 0; m < 8; m++) {
                f2u aa; aa.f = make_float2(am[m], am[m]);
#pragma unroll
                for (int p = 0; p < 4; p++) ffma2(acc[m][p], aa, b[p]);
            }
        }
        __syncthreads();
    }

    // epilogue: bias + relu, then store or atomicMax scatter
    float bb[8];
#pragma unroll
    for (int j = 0; j < 8; j++) bb[j] = bias[n0 + tn * 8 + j];

#pragma unroll
    for (int m = 0; m < 8; m++) {
        int gr = m0 + tm * 8 + m;
        if (gr < M) {
            float cv[8];
#pragma unroll
            for (int p = 0; p < 4; p++) { cv[2 * p] = acc[m][p].f.x; cv[2 * p + 1] = acc[m][p].f.y; }
#pragma unroll
            for (int j = 0; j < 8; j++) cv[j] = fmaxf(cv[j] + bb[j], 0.f);
            if (MODEE == 0) {
                float* dst = C + (size_t)gr * Ncol + n0 + tn * 8;
                *(float4*)(dst)     = make_float4(cv[0], cv[1], cv[2], cv[3]);
                *(float4*)(dst + 4) = make_float4(cv[4], cv[5], cv[6], cv[7]);
            } else {
                int v = idx[gr];
                int* dst = (int*)(C + (size_t)v * 256 + n0 + tn * 8);
#pragma unroll
                for (int j = 0; j < 8; j++) atomicMax(dst + j, __float_as_int(cv[j]));
            }
        }
    }
}

// ---------------------------------------------------------------------------
extern "C" void kernel_launch(void* const* d_in, const int* in_sizes, int n_in,
                              void* d_out, int out_size)
{
    const float* inp = (const float*)d_in[0];
    const int*   idx = (const int*)d_in[1];   // int32! (JAX x64 disabled)
    const float* W1  = (const float*)d_in[2];
    const float* b1  = (const float*)d_in[3];
    const float* W2  = (const float*)d_in[4];
    const float* b2  = (const float*)d_in[5];
    const float* Wv1 = (const float*)d_in[6];
    const float* bv1 = (const float*)d_in[7];
    const float* W3  = (const float*)d_in[8];
    const float* b3  = (const float*)d_in[9];
    const float* W4  = (const float*)d_in[10];
    const float* b4  = (const float*)d_in[11];
    const float* Wv2 = (const float*)d_in[12];
    const float* bv2 = (const float*)d_in[13];
    float* out = (float*)d_out;

    float *pf2, *vox1, *vox1g, *pf4, *vox2;
    cudaGetSymbolAddress((void**)&pf2,   g_pf2);
    cudaGetSymbolAddress((void**)&vox1,  g_vox1);
    cudaGetSymbolAddress((void**)&vox1g, g_vox1g);
    cudaGetSymbolAddress((void**)&pf4,   g_pf4);
    cudaGetSymbolAddress((void**)&vox2,  g_vox2);

    // 0) zero segment-max accumulators
    k_zero<<<2048, 256>>>();

    // 1) point MLP 6->64->128 + segment max into vox1
    k1_pointwise<<<(NPTS + 255) / 256, 256>>>(inp, idx, W1, b1, W2, b2);

    // 2) vox1g = relu(vox1 @ Wv1 + bv1)   [V,128]x[128,128]
    {
        dim3 g(NVOX / 128, 1);
        k_gemm<0, 0><<<g, 256>>>(vox1, nullptr, nullptr, nullptr, Wv1, bv1,
                                 vox1g, NVOX, 128, 128);
    }
    // 3) pf4 = relu(concat(vox1g[idx], pf2) @ W3 + b3)   [N,256]x[256,256]
    {
        dim3 g((NPTS + 127) / 128, 2);
        k_gemm<1, 0><<<g, 256>>>(nullptr, vox1g, pf2, idx, W3, b3,
                                 pf4, NPTS, 256, 256);
    }
    // 4) pf5 = relu(pf4 @ W4 + b4), segment max into vox2
    {
        dim3 g((NPTS + 127) / 128, 2);
        k_gemm<0, 1><<<g, 256>>>(pf4, nullptr, nullptr, idx, W4, b4,
                                 vox2, NPTS, 256, 256);
    }
    // 5) out = relu(vox2 @ Wv2 + bv2)   [V,256]x[256,256]
    {
        dim3 g(NVOX / 128, 2);
        k_gemm<0, 0><<<g, 256>>>(vox2, nullptr, nullptr, nullptr, Wv2, bv2,
                                 out, NVOX, 256, 256);
    }
}

// round 5
// speedup vs baseline: 1.8539x; 1.8539x over previous
#include <cuda_runtime.h>
#include <cuda_bf16.h>
#include <cstdint>

#define NPTS 500000
#define NVOX 65536

// Scratch (allocation-free rule: __device__ globals)
static __device__ __align__(16) float g_pf2 [(size_t)NPTS * 128];
static __device__ __align__(16) float g_vox1[(size_t)NVOX * 128];
static __device__ __align__(16) float g_vox1g[(size_t)NVOX * 128];
static __device__ __align__(16) float g_pf4 [(size_t)NPTS * 256];
static __device__ __align__(16) float g_vox2[(size_t)NVOX * 256];
// Pre-transposed, hi/lo-split weights: [Wv1t 128x128][W3t 256x256][W4t][Wv2t]
static __device__ __align__(16) __nv_bfloat16 g_wth[212992];
static __device__ __align__(16) __nv_bfloat16 g_wtl[212992];

__device__ __forceinline__ uint32_t smem_u32(const void* p) {
    return (uint32_t)__cvta_generic_to_shared((void*)p);
}
__device__ __forceinline__ uint32_t pack_hi2(float a, float b) {
    __nv_bfloat162 p; p.x = __float2bfloat16(a); p.y = __float2bfloat16(b);
    return *reinterpret_cast<uint32_t*>(&p);
}
__device__ __forceinline__ void ldmx4(uint32_t* r, uint32_t addr) {
    asm volatile("ldmatrix.sync.aligned.m8n8.x4.shared.b16 {%0,%1,%2,%3}, [%4];"
                 : "=r"(r[0]), "=r"(r[1]), "=r"(r[2]), "=r"(r[3]) : "r"(addr));
}
__device__ __forceinline__ void mma16816(float* d, const uint32_t* a, uint32_t b0, uint32_t b1) {
    asm volatile(
        "mma.sync.aligned.m16n8k16.row.col.f32.bf16.bf16.f32 "
        "{%0,%1,%2,%3}, {%4,%5,%6,%7}, {%8,%9}, {%0,%1,%2,%3};"
        : "+f"(d[0]), "+f"(d[1]), "+f"(d[2]), "+f"(d[3])
        : "r"(a[0]), "r"(a[1]), "r"(a[2]), "r"(a[3]), "r"(b0), "r"(b1));
}

// ---------------------------------------------------------------------------
// Zero-init segment-max accumulators
// ---------------------------------------------------------------------------
__global__ void k_zero() {
    const size_t n4a = (size_t)NVOX * 128 / 4;
    const size_t n4b = (size_t)NVOX * 256 / 4;
    float4 z = make_float4(0.f, 0.f, 0.f, 0.f);
    size_t stride = (size_t)gridDim.x * blockDim.x;
    for (size_t j = (size_t)blockIdx.x * blockDim.x + threadIdx.x; j < n4a + n4b; j += stride) {
        if (j < n4a) ((float4*)g_vox1)[j] = z;
        else         ((float4*)g_vox2)[j - n4a] = z;
    }
}

// ---------------------------------------------------------------------------
// Weight prep: W[K,Nf] fp32 -> Wt[Nf,K] bf16 hi/lo split (transposed)
// ---------------------------------------------------------------------------
__global__ void k_prep(const float* __restrict__ Wv1, const float* __restrict__ W3,
                       const float* __restrict__ W4,  const float* __restrict__ Wv2) {
    int i = blockIdx.x * 256 + threadIdx.x;
    if (i >= 212992) return;
    const float* W; int K, Nf, j = i;
    if (i < 16384)       { W = Wv1; K = 128; Nf = 128; }
    else if (i < 81920)  { W = W3;  K = 256; Nf = 256; j = i - 16384; }
    else if (i < 147456) { W = W4;  K = 256; Nf = 256; j = i - 81920; }
    else                 { W = Wv2; K = 256; Nf = 256; j = i - 147456; }
    int n = j / K, k = j - n * K;
    float x = W[(size_t)k * Nf + n];
    __nv_bfloat16 hi = __float2bfloat16(x);
    __nv_bfloat16 lo = __float2bfloat16(x - __bfloat162float(hi));
    g_wth[i] = hi;
    g_wtl[i] = lo;
}

// ---------------------------------------------------------------------------
// K1: per-point MLP 6 -> 64 -> 128, store pf2, atomicMax into vox1
// ---------------------------------------------------------------------------
__global__ __launch_bounds__(256) void k1_pointwise(
    const float* __restrict__ inp, const int* __restrict__ idx,
    const float* __restrict__ W1, const float* __restrict__ b1,
    const float* __restrict__ W2, const float* __restrict__ b2)
{
    __shared__ __align__(16) float sW1[6 * 64];
    __shared__ __align__(16) float sb1[64];
    __shared__ __align__(16) float sW2[64 * 128];
    __shared__ __align__(16) float sb2[128];
    int t = threadIdx.x;
    for (int i = t; i < 6 * 64; i += 256) sW1[i] = W1[i];
    if (t < 64)  sb1[t] = b1[t];
    for (int i = t; i < 64 * 128; i += 256) sW2[i] = W2[i];
    if (t < 128) sb2[t] = b2[t];
    __syncthreads();

    int i = blockIdx.x * 256 + t;
    if (i >= NPTS) return;

    float x[6];
#pragma unroll
    for (int c = 0; c < 6; c++) x[c] = inp[(size_t)i * 6 + c];

    float pf1[64];
#pragma unroll
    for (int j = 0; j < 64; j++) {
        float a = sb1[j];
#pragma unroll
        for (int c = 0; c < 6; c++) a = fmaf(x[c], sW1[c * 64 + j], a);
        pf1[j] = fmaxf(a, 0.f);
    }

    int v = idx[i];
    float4* outrow = (float4*)(g_pf2 + (size_t)i * 128);
    int*    voxrow = (int*)(g_vox1 + (size_t)v * 128);
    const float4* sW2v = (const float4*)sW2;
    const float4* sb2v = (const float4*)sb2;

#pragma unroll 1
    for (int j4 = 0; j4 < 32; j4++) {
        float4 acc = sb2v[j4];
#pragma unroll
        for (int k = 0; k < 64; k++) {
            float4 w = sW2v[k * 32 + j4];
            float p = pf1[k];
            acc.x = fmaf(p, w.x, acc.x);
            acc.y = fmaf(p, w.y, acc.y);
            acc.z = fmaf(p, w.z, acc.z);
            acc.w = fmaf(p, w.w, acc.w);
        }
        acc.x = fmaxf(acc.x, 0.f); acc.y = fmaxf(acc.y, 0.f);
        acc.z = fmaxf(acc.z, 0.f); acc.w = fmaxf(acc.w, 0.f);
        outrow[j4] = acc;
        atomicMax(voxrow + j4 * 4 + 0, __float_as_int(acc.x));
        atomicMax(voxrow + j4 * 4 + 1, __float_as_int(acc.y));
        atomicMax(voxrow + j4 * 4 + 2, __float_as_int(acc.z));
        atomicMax(voxrow + j4 * 4 + 3, __float_as_int(acc.w));
    }
}

// ---------------------------------------------------------------------------
// HMMA GEMM: C[p, f] = relu( act[p, :] . Wt[f, :] + bias[f] )
// Block 128(p) x 128(f), K-chunk 32, 4 warps (warp tile 64x64), bf16 hi/lo
// 3-pass split with fp32 MMA accumulation. Double-buffered smem.
//   KCHUNKS: K/32
//   MODEB 0: A rows from act[p*K + k]
//   MODEB 1: k<128 from G[idx[p]*128+k], else act[p*128 + (k-128)]
//   MODEE 0: store C[p*Nf + f];  MODEE 1: atomicMax C[idx[p]*256 + f]
// Smem tile layout: [row][k] bf16, row stride 80B (64B data + 16B pad)
// ---------------------------------------------------------------------------
template <int KCHUNKS, int MODEB, int MODEE>
__global__ __launch_bounds__(128) void k_hmma(
    const float* __restrict__ act, const float* __restrict__ G,
    const int* __restrict__ idx,
    const __nv_bfloat16* __restrict__ wth, const __nv_bfloat16* __restrict__ wtl,
    const float* __restrict__ bias, float* __restrict__ C, int M, int Nf)
{
    constexpr int K = KCHUNKS * 32;
    constexpr int STG = 40960;                 // bytes per stage (4 tiles x 10240)
    constexpr int AH = 0, AL = 10240, BH = 20480, BL = 30720;
    constexpr int IDX_OFF = 2 * STG;           // sIdx int[128]

    extern __shared__ char sm[];
    int* sIdx = (int*)(sm + IDX_OFF);
    uint32_t smb = smem_u32(sm);

    int t = threadIdx.x;
    int lane = t & 31;
    int w = t >> 5;
    int wm = w & 1, wn = w >> 1;
    int p0 = blockIdx.x * 128;
    int f0 = blockIdx.y * 128;

    // cache idx for this block's 128 points
    if (MODEB == 1 || MODEE == 1) {
        if (t < 128) sIdx[t] = (p0 + t < M) ? idx[p0 + t] : 0;
        __syncthreads();
    }

    // ---- fill helpers (as lambdas) ----
    auto fillA = [&](int s, int c) {
        int k0 = c * 32;
        char* ah = sm + s * STG + AH;
        char* al = sm + s * STG + AL;
#pragma unroll
        for (int it = 0; it < 8; it++) {
            int e = t + it * 128;
            int row = e >> 3, q = e & 7;       // q: float4 index (k = q*4)
            int gp = p0 + row;
            float4 v = make_float4(0.f, 0.f, 0.f, 0.f);
            if (gp < M) {
                const float* src;
                if (MODEB == 0) {
                    src = act + (size_t)gp * K + k0 + q * 4;
                } else {
                    if (k0 < 128) src = G + (size_t)sIdx[row] * 128 + k0 + q * 4;
                    else          src = act + (size_t)gp * 128 + (k0 - 128) + q * 4;
                }
                v = *(const float4*)src;
            }
            float rx = v.x - __bfloat162float(__float2bfloat16(v.x));
            float ry = v.y - __bfloat162float(__float2bfloat16(v.y));
            float rz = v.z - __bfloat162float(__float2bfloat16(v.z));
            float rw = v.w - __bfloat162float(__float2bfloat16(v.w));
            uint2 hi = make_uint2(pack_hi2(v.x, v.y), pack_hi2(v.z, v.w));
            uint2 lo = make_uint2(pack_hi2(rx, ry), pack_hi2(rz, rw));
            *(uint2*)(ah + row * 80 + q * 8) = hi;
            *(uint2*)(al + row * 80 + q * 8) = lo;
        }
    };
    auto fillB = [&](int s, int c) {
        int k0 = c * 32;
        char* bh = sm + s * STG + BH;
        char* bl = sm + s * STG + BL;
#pragma unroll
        for (int it = 0; it < 4; it++) {
            int e = t + it * 128;
            int n = e >> 2, q = e & 3;         // q: uint4 (16B = 8 bf16)
            size_t goff = (size_t)(f0 + n) * K + k0 + q * 8;
            uint4 vh = *(const uint4*)(wth + goff);
            uint4 vl = *(const uint4*)(wtl + goff);
            *(uint4*)(bh + n * 80 + q * 16) = vh;
            *(uint4*)(bl + n * 80 + q * 16) = vl;
        }
    };

    float acc[4][8][4];
#pragma unroll
    for (int i = 0; i < 4; i++)
#pragma unroll
        for (int j = 0; j < 8; j++)
#pragma unroll
            for (int r = 0; r < 4; r++) acc[i][j][r] = 0.f;

    // ldmatrix lane address components
    int ar  = ((lane >> 3) & 1) * 8 + (lane & 7);   // A row within 16-tile
    int akb = (lane >> 4) * 16;                     // A k-byte half
    int bn  = (lane >> 4) * 8 + (lane & 7);         // B row within 16 n
    int bkb = ((lane >> 3) & 1) * 16;               // B k-byte half

    fillA(0, 0); fillB(0, 0);

#pragma unroll 1
    for (int c = 0; c < KCHUNKS; c++) {
        __syncthreads();
        int s = c & 1;
        uint32_t base = smb + s * STG;
#pragma unroll
        for (int ks = 0; ks < 2; ks++) {        // two k16 steps per chunk
            int kb = ks * 32;
            uint32_t a[4][4], bh[4][4], bx[4][4];
#pragma unroll
            for (int i = 0; i < 4; i++)
                ldmx4(a[i], base + AH + (uint32_t)(wm * 64 + i * 16 + ar) * 80 + kb + akb);
#pragma unroll
            for (int j2 = 0; j2 < 4; j2++)
                ldmx4(bh[j2], base + BH + (uint32_t)(wn * 64 + j2 * 16 + bn) * 80 + kb + bkb);
            // pass hh
#pragma unroll
            for (int i = 0; i < 4; i++)
#pragma unroll
                for (int j = 0; j < 8; j++)
                    mma16816(acc[i][j], a[i], bh[j >> 1][(j & 1) * 2], bh[j >> 1][(j & 1) * 2 + 1]);
            // pass hl (B lo)
#pragma unroll
            for (int j2 = 0; j2 < 4; j2++)
                ldmx4(bx[j2], base + BL + (uint32_t)(wn * 64 + j2 * 16 + bn) * 80 + kb + bkb);
#pragma unroll
            for (int i = 0; i < 4; i++)
#pragma unroll
                for (int j = 0; j < 8; j++)
                    mma16816(acc[i][j], a[i], bx[j >> 1][(j & 1) * 2], bx[j >> 1][(j & 1) * 2 + 1]);
            // pass lh (A lo)
#pragma unroll
            for (int i = 0; i < 4; i++)
                ldmx4(a[i], base + AL + (uint32_t)(wm * 64 + i * 16 + ar) * 80 + kb + akb);
#pragma unroll
            for (int i = 0; i < 4; i++)
#pragma unroll
                for (int j = 0; j < 8; j++)
                    mma16816(acc[i][j], a[i], bh[j >> 1][(j & 1) * 2], bh[j >> 1][(j & 1) * 2 + 1]);
        }
        if (c + 1 < KCHUNKS) { fillA(s ^ 1, c + 1); fillB(s ^ 1, c + 1); }
    }

    // ---- epilogue ----
#pragma unroll
    for (int i = 0; i < 4; i++) {
        int pa = p0 + wm * 64 + i * 16 + (lane >> 2);
        int pb = pa + 8;
#pragma unroll
        for (int j = 0; j < 8; j++) {
            int f = f0 + wn * 64 + j * 8 + (lane & 3) * 2;
            float2 bj = *(const float2*)(bias + f);
            float v0 = fmaxf(acc[i][j][0] + bj.x, 0.f);
            float v1 = fmaxf(acc[i][j][1] + bj.y, 0.f);
            float v2 = fmaxf(acc[i][j][2] + bj.x, 0.f);
            float v3 = fmaxf(acc[i][j][3] + bj.y, 0.f);
            if (MODEE == 0) {
                if (pa < M) *(float2*)(C + (size_t)pa * Nf + f) = make_float2(v0, v1);
                if (pb < M) *(float2*)(C + (size_t)pb * Nf + f) = make_float2(v2, v3);
            } else {
                if (pa < M) {
                    int* d = (int*)(C + (size_t)sIdx[pa - p0] * 256 + f);
                    atomicMax(d,     __float_as_int(v0));
                    atomicMax(d + 1, __float_as_int(v1));
                }
                if (pb < M) {
                    int* d = (int*)(C + (size_t)sIdx[pb - p0] * 256 + f);
                    atomicMax(d,     __float_as_int(v2));
                    atomicMax(d + 1, __float_as_int(v3));
                }
            }
        }
    }
}

// ---------------------------------------------------------------------------
extern "C" void kernel_launch(void* const* d_in, const int* in_sizes, int n_in,
                              void* d_out, int out_size)
{
    const float* inp = (const float*)d_in[0];
    const int*   idx = (const int*)d_in[1];   // int32 (JAX x64 disabled)
    const float* W1  = (const float*)d_in[2];
    const float* b1  = (const float*)d_in[3];
    const float* W2  = (const float*)d_in[4];
    const float* b2  = (const float*)d_in[5];
    const float* Wv1 = (const float*)d_in[6];
    const float* bv1 = (const float*)d_in[7];
    const float* W3  = (const float*)d_in[8];
    const float* b3  = (const float*)d_in[9];
    const float* W4  = (const float*)d_in[10];
    const float* b4  = (const float*)d_in[11];
    const float* Wv2 = (const float*)d_in[12];
    const float* bv2 = (const float*)d_in[13];
    float* out = (float*)d_out;

    float *pf2, *vox1, *vox1g, *pf4, *vox2;
    __nv_bfloat16 *wth, *wtl;
    cudaGetSymbolAddress((void**)&pf2,   g_pf2);
    cudaGetSymbolAddress((void**)&vox1,  g_vox1);
    cudaGetSymbolAddress((void**)&vox1g, g_vox1g);
    cudaGetSymbolAddress((void**)&pf4,   g_pf4);
    cudaGetSymbolAddress((void**)&vox2,  g_vox2);
    cudaGetSymbolAddress((void**)&wth,   g_wth);
    cudaGetSymbolAddress((void**)&wtl,   g_wtl);

    const int SMEM = 2 * 40960 + 512;
    cudaFuncSetAttribute(k_hmma<4,0,0>, cudaFuncAttributeMaxDynamicSharedMemorySize, SMEM);
    cudaFuncSetAttribute(k_hmma<8,1,0>, cudaFuncAttributeMaxDynamicSharedMemorySize, SMEM);
    cudaFuncSetAttribute(k_hmma<8,0,1>, cudaFuncAttributeMaxDynamicSharedMemorySize, SMEM);
    cudaFuncSetAttribute(k_hmma<8,0,0>, cudaFuncAttributeMaxDynamicSharedMemorySize, SMEM);

    // 0) zero segment-max accumulators + prep weights
    k_zero<<<2048, 256>>>();
    k_prep<<<(212992 + 255) / 256, 256>>>(Wv1, W3, W4, Wv2);

    // 1) point MLP 6->64->128 + segment max into vox1
    k1_pointwise<<<(NPTS + 255) / 256, 256>>>(inp, idx, W1, b1, W2, b2);

    // 2) vox1g = relu(vox1 @ Wv1 + bv1)   [V,128] K=128
    k_hmma<4,0,0><<<dim3(NVOX / 128, 1), 128, SMEM>>>(
        vox1, nullptr, nullptr, wth + 0, wtl + 0, bv1, vox1g, NVOX, 128);
    // 3) pf4 = relu(concat(vox1g[idx], pf2) @ W3 + b3)   [N,256] K=256
    k_hmma<8,1,0><<<dim3((NPTS + 127) / 128, 2), 128, SMEM>>>(
        pf2, vox1g, idx, wth + 16384, wtl + 16384, b3, pf4, NPTS, 256);
    // 4) pf5 = relu(pf4 @ W4 + b4) -> atomicMax into vox2
    k_hmma<8,0,1><<<dim3((NPTS + 127) / 128, 2), 128, SMEM>>>(
        pf4, nullptr, idx, wth + 81920, wtl + 81920, b4, vox2, NPTS, 256);
    // 5) out = relu(vox2 @ Wv2 + bv2)   [V,256] K=256
    k_hmma<8,0,0><<<dim3(NVOX / 128, 2), 128, SMEM>>>(
        vox2, nullptr, nullptr, wth + 147456, wtl + 147456, bv2, out, NVOX, 256);
}

// round 6
// speedup vs baseline: 2.1290x; 1.1484x over previous
#include <cuda_runtime.h>
#include <cuda_bf16.h>
#include <cstdint>

#define NPTS 500000
#define NVOX 65536

// fp32 accumulators for atomic segment-max
static __device__ __align__(16) float g_vox1[(size_t)NVOX * 128];
static __device__ __align__(16) float g_vox2[(size_t)NVOX * 256];
// bf16 hi/lo activation mirrors
static __device__ __align__(16) __nv_bfloat16 g_pf2h [(size_t)NPTS * 128];
static __device__ __align__(16) __nv_bfloat16 g_pf2l [(size_t)NPTS * 128];
static __device__ __align__(16) __nv_bfloat16 g_vox1h[(size_t)NVOX * 128];
static __device__ __align__(16) __nv_bfloat16 g_vox1l[(size_t)NVOX * 128];
static __device__ __align__(16) __nv_bfloat16 g_vgh  [(size_t)NVOX * 128];
static __device__ __align__(16) __nv_bfloat16 g_vgl  [(size_t)NVOX * 128];
static __device__ __align__(16) __nv_bfloat16 g_pf4h [(size_t)NPTS * 256];
static __device__ __align__(16) __nv_bfloat16 g_pf4l [(size_t)NPTS * 256];
static __device__ __align__(16) __nv_bfloat16 g_vox2h[(size_t)NVOX * 256];
static __device__ __align__(16) __nv_bfloat16 g_vox2l[(size_t)NVOX * 256];
// Pre-transposed, hi/lo-split weights: [Wv1t 128x128][W3t 256x256][W4t][Wv2t]
static __device__ __align__(16) __nv_bfloat16 g_wth[212992];
static __device__ __align__(16) __nv_bfloat16 g_wtl[212992];

__device__ __forceinline__ uint32_t smem_u32(const void* p) {
    return (uint32_t)__cvta_generic_to_shared((void*)p);
}
__device__ __forceinline__ uint32_t pack_hi2(float a, float b) {
    __nv_bfloat162 p; p.x = __float2bfloat16(a); p.y = __float2bfloat16(b);
    return *reinterpret_cast<uint32_t*>(&p);
}
__device__ __forceinline__ float bflo(float v) {   // residual after bf16 truncation
    return v - __bfloat162float(__float2bfloat16(v));
}
__device__ __forceinline__ void ldmx4(uint32_t* r, uint32_t addr) {
    asm volatile("ldmatrix.sync.aligned.m8n8.x4.shared.b16 {%0,%1,%2,%3}, [%4];"
                 : "=r"(r[0]), "=r"(r[1]), "=r"(r[2]), "=r"(r[3]) : "r"(addr));
}
__device__ __forceinline__ void mma16816(float* d, const uint32_t* a, uint32_t b0, uint32_t b1) {
    asm volatile(
        "mma.sync.aligned.m16n8k16.row.col.f32.bf16.bf16.f32 "
        "{%0,%1,%2,%3}, {%4,%5,%6,%7}, {%8,%9}, {%0,%1,%2,%3};"
        : "+f"(d[0]), "+f"(d[1]), "+f"(d[2]), "+f"(d[3])
        : "r"(a[0]), "r"(a[1]), "r"(a[2]), "r"(a[3]), "r"(b0), "r"(b1));
}
__device__ __forceinline__ void cp16(uint32_t dst, const void* src, bool pred) {
    int sz = pred ? 16 : 0;
    asm volatile("cp.async.cg.shared.global [%0], [%1], 16, %2;"
                 :: "r"(dst), "l"(src), "r"(sz));
}
__device__ __forceinline__ void cp_commit() { asm volatile("cp.async.commit_group;"); }
__device__ __forceinline__ void cp_wait0()  { asm volatile("cp.async.wait_group 0;" ::: "memory"); }

// ---------------------------------------------------------------------------
__global__ void k_zero() {
    const size_t n4a = (size_t)NVOX * 128 / 4;
    const size_t n4b = (size_t)NVOX * 256 / 4;
    float4 z = make_float4(0.f, 0.f, 0.f, 0.f);
    size_t stride = (size_t)gridDim.x * blockDim.x;
    for (size_t j = (size_t)blockIdx.x * blockDim.x + threadIdx.x; j < n4a + n4b; j += stride) {
        if (j < n4a) ((float4*)g_vox1)[j] = z;
        else         ((float4*)g_vox2)[j - n4a] = z;
    }
}

// fp32 -> bf16 hi/lo split, vectorized by 4
__global__ void k_cvt(const float* __restrict__ src, __nv_bfloat16* __restrict__ dh,
                      __nv_bfloat16* __restrict__ dl, int n4) {
    int i = blockIdx.x * 256 + threadIdx.x;
    if (i >= n4) return;
    float4 v = ((const float4*)src)[i];
    *(uint2*)(dh + (size_t)i * 4) = make_uint2(pack_hi2(v.x, v.y), pack_hi2(v.z, v.w));
    *(uint2*)(dl + (size_t)i * 4) = make_uint2(pack_hi2(bflo(v.x), bflo(v.y)),
                                               pack_hi2(bflo(v.z), bflo(v.w)));
}

// Weight prep: W[K,Nf] fp32 -> Wt[Nf,K] bf16 hi/lo split (transposed)
__global__ void k_prep(const float* __restrict__ Wv1, const float* __restrict__ W3,
                       const float* __restrict__ W4,  const float* __restrict__ Wv2) {
    int i = blockIdx.x * 256 + threadIdx.x;
    if (i >= 212992) return;
    const float* W; int K, Nf, j = i;
    if (i < 16384)       { W = Wv1; K = 128; Nf = 128; }
    else if (i < 81920)  { W = W3;  K = 256; Nf = 256; j = i - 16384; }
    else if (i < 147456) { W = W4;  K = 256; Nf = 256; j = i - 81920; }
    else                 { W = Wv2; K = 256; Nf = 256; j = i - 147456; }
    int n = j / K, k = j - n * K;
    float x = W[(size_t)k * Nf + n];
    g_wth[i] = __float2bfloat16(x);
    g_wtl[i] = __float2bfloat16(bflo(x));
}

// ---------------------------------------------------------------------------
// K1: per-point MLP 6 -> 64 -> 128, write pf2 hi/lo bf16, atomicMax into vox1
// ---------------------------------------------------------------------------
__global__ __launch_bounds__(256) void k1_pointwise(
    const float* __restrict__ inp, const int* __restrict__ idx,
    const float* __restrict__ W1, const float* __restrict__ b1,
    const float* __restrict__ W2, const float* __restrict__ b2)
{
    __shared__ __align__(16) float sW1[6 * 64];
    __shared__ __align__(16) float sb1[64];
    __shared__ __align__(16) float sW2[64 * 128];
    __shared__ __align__(16) float sb2[128];
    int t = threadIdx.x;
    for (int i = t; i < 6 * 64; i += 256) sW1[i] = W1[i];
    if (t < 64)  sb1[t] = b1[t];
    for (int i = t; i < 64 * 128; i += 256) sW2[i] = W2[i];
    if (t < 128) sb2[t] = b2[t];
    __syncthreads();

    int i = blockIdx.x * 256 + t;
    if (i >= NPTS) return;

    float x[6];
#pragma unroll
    for (int c = 0; c < 6; c++) x[c] = inp[(size_t)i * 6 + c];

    float pf1[64];
#pragma unroll
    for (int j = 0; j < 64; j++) {
        float a = sb1[j];
#pragma unroll
        for (int c = 0; c < 6; c++) a = fmaf(x[c], sW1[c * 64 + j], a);
        pf1[j] = fmaxf(a, 0.f);
    }

    int v = idx[i];
    int* voxrow = (int*)(g_vox1 + (size_t)v * 128);
    const float4* sW2v = (const float4*)sW2;
    const float4* sb2v = (const float4*)sb2;

#pragma unroll 1
    for (int j4 = 0; j4 < 32; j4++) {
        float4 acc = sb2v[j4];
#pragma unroll
        for (int k = 0; k < 64; k++) {
            float4 w = sW2v[k * 32 + j4];
            float p = pf1[k];
            acc.x = fmaf(p, w.x, acc.x);
            acc.y = fmaf(p, w.y, acc.y);
            acc.z = fmaf(p, w.z, acc.z);
            acc.w = fmaf(p, w.w, acc.w);
        }
        acc.x = fmaxf(acc.x, 0.f); acc.y = fmaxf(acc.y, 0.f);
        acc.z = fmaxf(acc.z, 0.f); acc.w = fmaxf(acc.w, 0.f);
        size_t off = (size_t)i * 128 + j4 * 4;
        *(uint2*)(g_pf2h + off) = make_uint2(pack_hi2(acc.x, acc.y), pack_hi2(acc.z, acc.w));
        *(uint2*)(g_pf2l + off) = make_uint2(pack_hi2(bflo(acc.x), bflo(acc.y)),
                                             pack_hi2(bflo(acc.z), bflo(acc.w)));
        atomicMax(voxrow + j4 * 4 + 0, __float_as_int(acc.x));
        atomicMax(voxrow + j4 * 4 + 1, __float_as_int(acc.y));
        atomicMax(voxrow + j4 * 4 + 2, __float_as_int(acc.z));
        atomicMax(voxrow + j4 * 4 + 3, __float_as_int(acc.w));
    }
}

// ---------------------------------------------------------------------------
// HMMA GEMM with cp.async fills: C[p,f] = relu( act[p,:] . Wt[f,:] + bias[f] )
// Block 128x128, K-chunk 32, 4 warps (64x64 warp tile), bf16 hi/lo 3-pass.
//   MODEB 0: A rows from ah/al[p*K + k]
//   MODEB 1: k<128 from gh/gl[idx[p]*128+k], else ah/al[p*128 + (k-128)]
//   MODEE 0: store fp32 C (CVTOUT: also/instead write Ch/Cl bf16 hi/lo)
//   MODEE 1: atomicMax into C[idx[p]*256 + f]
// ---------------------------------------------------------------------------
template <int KCHUNKS, int MODEB, int MODEE, int CVTOUT>
__global__ __launch_bounds__(128) void k_hmma(
    const __nv_bfloat16* __restrict__ ah, const __nv_bfloat16* __restrict__ al,
    const __nv_bfloat16* __restrict__ gh, const __nv_bfloat16* __restrict__ gl,
    const int* __restrict__ idx,
    const __nv_bfloat16* __restrict__ wth, const __nv_bfloat16* __restrict__ wtl,
    const float* __restrict__ bias,
    float* __restrict__ C, __nv_bfloat16* __restrict__ Ch, __nv_bfloat16* __restrict__ Cl,
    int M, int Nf)
{
    constexpr int K = KCHUNKS * 32;
    constexpr int STG = 40960;                 // 4 tiles x 10240 (128 rows x 80B)
    constexpr int AH = 0, AL = 10240, BH = 20480, BL = 30720;
    constexpr int IDX_OFF = 2 * STG;

    extern __shared__ char sm[];
    int* sIdx = (int*)(sm + IDX_OFF);
    uint32_t smb = smem_u32(sm);

    int t = threadIdx.x;
    int lane = t & 31;
    int w = t >> 5;
    int wm = w & 1, wn = w >> 1;
    int p0 = blockIdx.x * 128;
    int f0 = blockIdx.y * 128;

    if (MODEB == 1 || MODEE == 1) {
        if (t < 128) sIdx[t] = (p0 + t < M) ? idx[p0 + t] : 0;
        __syncthreads();
    }

    auto fill = [&](int s, int c) {
        int k0 = c * 32;
        uint32_t base = smb + s * STG;
        // A tiles (hi: e<512, lo: e>=512); 16B seg per cp.async
#pragma unroll
        for (int it = 0; it < 8; it++) {
            int e = t + it * 128;
            int half = e >> 9;
            int row = (e >> 2) & 127;
            int q = e & 3;
            uint32_t dst = base + (half ? AL : AH) + row * 80 + q * 16;
            int gp = p0 + row;
            const __nv_bfloat16* srcp;
            if (MODEB == 0) {
                srcp = (half ? al : ah) + (size_t)gp * K + k0 + q * 8;
            } else {
                if (k0 < 128) srcp = (half ? gl : gh) + (size_t)sIdx[row] * 128 + k0 + q * 8;
                else          srcp = (half ? al : ah) + (size_t)gp * 128 + (k0 - 128) + q * 8;
            }
            cp16(dst, srcp, gp < M);
        }
        // B tiles (weights, always in range)
#pragma unroll
        for (int it = 0; it < 8; it++) {
            int e = t + it * 128;
            int half = e >> 9;
            int n = (e >> 2) & 127;
            int q = e & 3;
            uint32_t dst = base + (half ? BL : BH) + n * 80 + q * 16;
            const __nv_bfloat16* srcp = (half ? wtl : wth) + (size_t)(f0 + n) * K + k0 + q * 8;
            cp16(dst, srcp, true);
        }
        cp_commit();
    };

    float acc[4][8][4];
#pragma unroll
    for (int i = 0; i < 4; i++)
#pragma unroll
        for (int j = 0; j < 8; j++)
#pragma unroll
            for (int r = 0; r < 4; r++) acc[i][j][r] = 0.f;

    int ar  = ((lane >> 3) & 1) * 8 + (lane & 7);
    int akb = (lane >> 4) * 16;
    int bn  = (lane >> 4) * 8 + (lane & 7);
    int bkb = ((lane >> 3) & 1) * 16;

    fill(0, 0);

#pragma unroll 1
    for (int c = 0; c < KCHUNKS; c++) {
        cp_wait0();
        __syncthreads();
        if (c + 1 < KCHUNKS) fill((c + 1) & 1, c + 1);
        int s = c & 1;
        uint32_t base = smb + s * STG;
#pragma unroll
        for (int ks = 0; ks < 2; ks++) {
            int kb = ks * 32;
            uint32_t a[4][4], bh[4][4], bx[4][4];
#pragma unroll
            for (int i = 0; i < 4; i++)
                ldmx4(a[i], base + AH + (uint32_t)(wm * 64 + i * 16 + ar) * 80 + kb + akb);
#pragma unroll
            for (int j2 = 0; j2 < 4; j2++)
                ldmx4(bh[j2], base + BH + (uint32_t)(wn * 64 + j2 * 16 + bn) * 80 + kb + bkb);
#pragma unroll
            for (int i = 0; i < 4; i++)
#pragma unroll
                for (int j = 0; j < 8; j++)
                    mma16816(acc[i][j], a[i], bh[j >> 1][(j & 1) * 2], bh[j >> 1][(j & 1) * 2 + 1]);
#pragma unroll
            for (int j2 = 0; j2 < 4; j2++)
                ldmx4(bx[j2], base + BL + (uint32_t)(wn * 64 + j2 * 16 + bn) * 80 + kb + bkb);
#pragma unroll
            for (int i = 0; i < 4; i++)
#pragma unroll
                for (int j = 0; j < 8; j++)
                    mma16816(acc[i][j], a[i], bx[j >> 1][(j & 1) * 2], bx[j >> 1][(j & 1) * 2 + 1]);
#pragma unroll
            for (int i = 0; i < 4; i++)
                ldmx4(a[i], base + AL + (uint32_t)(wm * 64 + i * 16 + ar) * 80 + kb + akb);
#pragma unroll
            for (int i = 0; i < 4; i++)
#pragma unroll
                for (int j = 0; j < 8; j++)
                    mma16816(acc[i][j], a[i], bh[j >> 1][(j & 1) * 2], bh[j >> 1][(j & 1) * 2 + 1]);
        }
        __syncthreads();
    }

    // ---- epilogue ----
#pragma unroll
    for (int i = 0; i < 4; i++) {
        int pa = p0 + wm * 64 + i * 16 + (lane >> 2);
        int pb = pa + 8;
#pragma unroll
        for (int j = 0; j < 8; j++) {
            int f = f0 + wn * 64 + j * 8 + (lane & 3) * 2;
            float2 bj = *(const float2*)(bias + f);
            float v0 = fmaxf(acc[i][j][0] + bj.x, 0.f);
            float v1 = fmaxf(acc[i][j][1] + bj.y, 0.f);
            float v2 = fmaxf(acc[i][j][2] + bj.x, 0.f);
            float v3 = fmaxf(acc[i][j][3] + bj.y, 0.f);
            if (MODEE == 0) {
                if (CVTOUT) {
                    if (pa < M) {
                        size_t o = (size_t)pa * Nf + f;
                        *(uint32_t*)(Ch + o) = pack_hi2(v0, v1);
                        *(uint32_t*)(Cl + o) = pack_hi2(bflo(v0), bflo(v1));
                    }
                    if (pb < M) {
                        size_t o = (size_t)pb * Nf + f;
                        *(uint32_t*)(Ch + o) = pack_hi2(v2, v3);
                        *(uint32_t*)(Cl + o) = pack_hi2(bflo(v2), bflo(v3));
                    }
                } else {
                    if (pa < M) *(float2*)(C + (size_t)pa * Nf + f) = make_float2(v0, v1);
                    if (pb < M) *(float2*)(C + (size_t)pb * Nf + f) = make_float2(v2, v3);
                }
            } else {
                if (pa < M) {
                    int* d = (int*)(C + (size_t)sIdx[pa - p0] * 256 + f);
                    atomicMax(d,     __float_as_int(v0));
                    atomicMax(d + 1, __float_as_int(v1));
                }
                if (pb < M) {
                    int* d = (int*)(C + (size_t)sIdx[pb - p0] * 256 + f);
                    atomicMax(d,     __float_as_int(v2));
                    atomicMax(d + 1, __float_as_int(v3));
                }
            }
        }
    }
}

// ---------------------------------------------------------------------------
extern "C" void kernel_launch(void* const* d_in, const int* in_sizes, int n_in,
                              void* d_out, int out_size)
{
    const float* inp = (const float*)d_in[0];
    const int*   idx = (const int*)d_in[1];   // int32 (JAX x64 disabled)
    const float* W1  = (const float*)d_in[2];
    const float* b1  = (const float*)d_in[3];
    const float* W2  = (const float*)d_in[4];
    const float* b2  = (const float*)d_in[5];
    const float* Wv1 = (const float*)d_in[6];
    const float* bv1 = (const float*)d_in[7];
    const float* W3  = (const float*)d_in[8];
    const float* b3  = (const float*)d_in[9];
    const float* W4  = (const float*)d_in[10];
    const float* b4  = (const float*)d_in[11];
    const float* Wv2 = (const float*)d_in[12];
    const float* bv2 = (const float*)d_in[13];
    float* out = (float*)d_out;

    float *vox1, *vox2;
    __nv_bfloat16 *pf2h, *pf2l, *vox1h, *vox1l, *vgh, *vgl, *pf4h, *pf4l, *vox2h, *vox2l, *wth, *wtl;
    cudaGetSymbolAddress((void**)&vox1,  g_vox1);
    cudaGetSymbolAddress((void**)&vox2,  g_vox2);
    cudaGetSymbolAddress((void**)&pf2h,  g_pf2h);
    cudaGetSymbolAddress((void**)&pf2l,  g_pf2l);
    cudaGetSymbolAddress((void**)&vox1h, g_vox1h);
    cudaGetSymbolAddress((void**)&vox1l, g_vox1l);
    cudaGetSymbolAddress((void**)&vgh,   g_vgh);
    cudaGetSymbolAddress((void**)&vgl,   g_vgl);
    cudaGetSymbolAddress((void**)&pf4h,  g_pf4h);
    cudaGetSymbolAddress((void**)&pf4l,  g_pf4l);
    cudaGetSymbolAddress((void**)&vox2h, g_vox2h);
    cudaGetSymbolAddress((void**)&vox2l, g_vox2l);
    cudaGetSymbolAddress((void**)&wth,   g_wth);
    cudaGetSymbolAddress((void**)&wtl,   g_wtl);

    const int SMEM = 2 * 40960 + 512;
    cudaFuncSetAttribute(k_hmma<4,0,0,1>, cudaFuncAttributeMaxDynamicSharedMemorySize, SMEM);
    cudaFuncSetAttribute(k_hmma<8,1,0,1>, cudaFuncAttributeMaxDynamicSharedMemorySize, SMEM);
    cudaFuncSetAttribute(k_hmma<8,0,1,0>, cudaFuncAttributeMaxDynamicSharedMemorySize, SMEM);
    cudaFuncSetAttribute(k_hmma<8,0,0,0>, cudaFuncAttributeMaxDynamicSharedMemorySize, SMEM);

    // 0) zero accumulators, prep weights
    k_zero<<<2048, 256>>>();
    k_prep<<<(212992 + 255) / 256, 256>>>(Wv1, W3, W4, Wv2);

    // 1) point MLP -> pf2 hi/lo + atomic max into vox1
    k1_pointwise<<<(NPTS + 255) / 256, 256>>>(inp, idx, W1, b1, W2, b2);

    // 1b) split vox1 fp32 -> bf16 hi/lo
    k_cvt<<<(NVOX * 128 / 4 + 255) / 256, 256>>>(vox1, vox1h, vox1l, NVOX * 128 / 4);

    // 2) vg = relu(vox1 @ Wv1 + bv1)  -> bf16 hi/lo
    k_hmma<4,0,0,1><<<dim3(NVOX / 128, 1), 128, SMEM>>>(
        vox1h, vox1l, nullptr, nullptr, nullptr, wth + 0, wtl + 0, bv1,
        nullptr, vgh, vgl, NVOX, 128);
    // 3) pf4 = relu(concat(vg[idx], pf2) @ W3 + b3) -> bf16 hi/lo
    k_hmma<8,1,0,1><<<dim3((NPTS + 127) / 128, 2), 128, SMEM>>>(
        pf2h, pf2l, vgh, vgl, idx, wth + 16384, wtl + 16384, b3,
        nullptr, pf4h, pf4l, NPTS, 256);
    // 4) pf5 = relu(pf4 @ W4 + b4) -> atomicMax into vox2 (fp32)
    k_hmma<8,0,1,0><<<dim3((NPTS + 127) / 128, 2), 128, SMEM>>>(
        pf4h, pf4l, nullptr, nullptr, idx, wth + 81920, wtl + 81920, b4,
        vox2, nullptr, nullptr, NPTS, 256);
    // 4b) split vox2
    k_cvt<<<(NVOX * 256 / 4 + 255) / 256, 256>>>(vox2, vox2h, vox2l, NVOX * 256 / 4);
    // 5) out = relu(vox2 @ Wv2 + bv2)  (fp32 store)
    k_hmma<8,0,0,0><<<dim3(NVOX / 128, 2), 128, SMEM>>>(
        vox2h, vox2l, nullptr, nullptr, nullptr, wth + 147456, wtl + 147456, bv2,
        out, nullptr, nullptr, NVOX, 256);
}

// round 7
// speedup vs baseline: 2.8175x; 1.3234x over previous
#include <cuda_runtime.h>
#include <cuda_fp16.h>
#include <cstdint>

#define NPTS 500000
#define NVOX 65536

// fp32 accumulators for atomic segment-max
static __device__ __align__(16) float g_vox1[(size_t)NVOX * 128];
static __device__ __align__(16) float g_vox2[(size_t)NVOX * 256];
// fp16 activation mirrors (single copy; the hi/lo split lives in the weights)
static __device__ __align__(16) __half g_pf2h [(size_t)NPTS * 128];
static __device__ __align__(16) __half g_vox1h[(size_t)NVOX * 128];
static __device__ __align__(16) __half g_vgh  [(size_t)NVOX * 128];
static __device__ __align__(16) __half g_pf4h [(size_t)NPTS * 256];
static __device__ __align__(16) __half g_vox2h[(size_t)NVOX * 256];
// Pre-transposed fp16 hi/lo weights: [Wv1t 128x128][W3t 256x256][W4t][Wv2t]
static __device__ __align__(16) __half g_wth[212992];
static __device__ __align__(16) __half g_wtl[212992];

__device__ __forceinline__ uint32_t smem_u32(const void* p) {
    return (uint32_t)__cvta_generic_to_shared((void*)p);
}
__device__ __forceinline__ uint32_t packh2(float a, float b) {
    __half2 p = __floats2half2_rn(a, b);
    return *reinterpret_cast<uint32_t*>(&p);
}
__device__ __forceinline__ void ldmx4(uint32_t* r, uint32_t addr) {
    asm volatile("ldmatrix.sync.aligned.m8n8.x4.shared.b16 {%0,%1,%2,%3}, [%4];"
                 : "=r"(r[0]), "=r"(r[1]), "=r"(r[2]), "=r"(r[3]) : "r"(addr));
}
__device__ __forceinline__ void mma16816(float* d, const uint32_t* a, uint32_t b0, uint32_t b1) {
    asm volatile(
        "mma.sync.aligned.m16n8k16.row.col.f32.f16.f16.f32 "
        "{%0,%1,%2,%3}, {%4,%5,%6,%7}, {%8,%9}, {%0,%1,%2,%3};"
        : "+f"(d[0]), "+f"(d[1]), "+f"(d[2]), "+f"(d[3])
        : "r"(a[0]), "r"(a[1]), "r"(a[2]), "r"(a[3]), "r"(b0), "r"(b1));
}
__device__ __forceinline__ void cp16(uint32_t dst, const void* src, bool pred) {
    int sz = pred ? 16 : 0;
    asm volatile("cp.async.cg.shared.global [%0], [%1], 16, %2;"
                 :: "r"(dst), "l"(src), "r"(sz));
}
__device__ __forceinline__ void cp_commit() { asm volatile("cp.async.commit_group;"); }
__device__ __forceinline__ void cp_wait0()  { asm volatile("cp.async.wait_group 0;" ::: "memory"); }
__device__ __forceinline__ void cp_wait1()  { asm volatile("cp.async.wait_group 1;" ::: "memory"); }

// ---------------------------------------------------------------------------
__global__ void k_zero() {
    const size_t n4a = (size_t)NVOX * 128 / 4;
    const size_t n4b = (size_t)NVOX * 256 / 4;
    float4 z = make_float4(0.f, 0.f, 0.f, 0.f);
    size_t stride = (size_t)gridDim.x * blockDim.x;
    for (size_t j = (size_t)blockIdx.x * blockDim.x + threadIdx.x; j < n4a + n4b; j += stride) {
        if (j < n4a) ((float4*)g_vox1)[j] = z;
        else         ((float4*)g_vox2)[j - n4a] = z;
    }
}

// fp32 -> fp16, vectorized by 4
__global__ void k_cvt(const float* __restrict__ src, __half* __restrict__ dh, int n4) {
    int i = blockIdx.x * 256 + threadIdx.x;
    if (i >= n4) return;
    float4 v = ((const float4*)src)[i];
    *(uint2*)(dh + (size_t)i * 4) = make_uint2(packh2(v.x, v.y), packh2(v.z, v.w));
}

// Weight prep: W[K,Nf] fp32 -> Wt[Nf,K] fp16 hi/lo split (transposed)
__global__ void k_prep(const float* __restrict__ Wv1, const float* __restrict__ W3,
                       const float* __restrict__ W4,  const float* __restrict__ Wv2) {
    int i = blockIdx.x * 256 + threadIdx.x;
    if (i >= 212992) return;
    const float* W; int K, Nf, j = i;
    if (i < 16384)       { W = Wv1; K = 128; Nf = 128; }
    else if (i < 81920)  { W = W3;  K = 256; Nf = 256; j = i - 16384; }
    else if (i < 147456) { W = W4;  K = 256; Nf = 256; j = i - 81920; }
    else                 { W = Wv2; K = 256; Nf = 256; j = i - 147456; }
    int n = j / K, k = j - n * K;
    float x = W[(size_t)k * Nf + n];
    __half hi = __float2half_rn(x);
    g_wth[i] = hi;
    g_wtl[i] = __float2half_rn(x - __half2float(hi));
}

// ---------------------------------------------------------------------------
// K1: per-point MLP 6 -> 64 -> 128, write pf2 fp16, atomicMax into vox1
// ---------------------------------------------------------------------------
__global__ __launch_bounds__(256) void k1_pointwise(
    const float* __restrict__ inp, const int* __restrict__ idx,
    const float* __restrict__ W1, const float* __restrict__ b1,
    const float* __restrict__ W2, const float* __restrict__ b2)
{
    __shared__ __align__(16) float sW1[6 * 64];
    __shared__ __align__(16) float sb1[64];
    __shared__ __align__(16) float sW2[64 * 128];
    __shared__ __align__(16) float sb2[128];
    int t = threadIdx.x;
    for (int i = t; i < 6 * 64; i += 256) sW1[i] = W1[i];
    if (t < 64)  sb1[t] = b1[t];
    for (int i = t; i < 64 * 128; i += 256) sW2[i] = W2[i];
    if (t < 128) sb2[t] = b2[t];
    __syncthreads();

    int i = blockIdx.x * 256 + t;
    if (i >= NPTS) return;

    float x[6];
#pragma unroll
    for (int c = 0; c < 6; c++) x[c] = inp[(size_t)i * 6 + c];

    float pf1[64];
#pragma unroll
    for (int j = 0; j < 64; j++) {
        float a = sb1[j];
#pragma unroll
        for (int c = 0; c < 6; c++) a = fmaf(x[c], sW1[c * 64 + j], a);
        pf1[j] = fmaxf(a, 0.f);
    }

    int v = idx[i];
    int* voxrow = (int*)(g_vox1 + (size_t)v * 128);
    const float4* sW2v = (const float4*)sW2;
    const float4* sb2v = (const float4*)sb2;

#pragma unroll 1
    for (int j4 = 0; j4 < 32; j4++) {
        float4 acc = sb2v[j4];
#pragma unroll
        for (int k = 0; k < 64; k++) {
            float4 w = sW2v[k * 32 + j4];
            float p = pf1[k];
            acc.x = fmaf(p, w.x, acc.x);
            acc.y = fmaf(p, w.y, acc.y);
            acc.z = fmaf(p, w.z, acc.z);
            acc.w = fmaf(p, w.w, acc.w);
        }
        acc.x = fmaxf(acc.x, 0.f); acc.y = fmaxf(acc.y, 0.f);
        acc.z = fmaxf(acc.z, 0.f); acc.w = fmaxf(acc.w, 0.f);
        *(uint2*)(g_pf2h + (size_t)i * 128 + j4 * 4) =
            make_uint2(packh2(acc.x, acc.y), packh2(acc.z, acc.w));
        atomicMax(voxrow + j4 * 4 + 0, __float_as_int(acc.x));
        atomicMax(voxrow + j4 * 4 + 1, __float_as_int(acc.y));
        atomicMax(voxrow + j4 * 4 + 2, __float_as_int(acc.z));
        atomicMax(voxrow + j4 * 4 + 3, __float_as_int(acc.w));
    }
}

// ---------------------------------------------------------------------------
// HMMA GEMM, fp16 2-pass: C[p,f] = relu( A[p,:] . (Wh+Wl)[f,:] + bias[f] )
// Block 128x128, K-chunk 32, 4 warps (64x64 warp tile), 3-stage cp.async.
//   MODEB 0: A rows from ah[p*K + k]
//   MODEB 1: k<128 from gh[idx[p]*128+k], else ah[p*128 + (k-128)]
//   MODEE 0: store (CVTOUT ? fp16 Ch : fp32 C)
//   MODEE 1: atomicMax into C[idx[p]*256 + f]
// Stage layout: A[128x80B] @0, BH @10240, BL @20480  (stage = 30720B)
// ---------------------------------------------------------------------------
template <int KCHUNKS, int MODEB, int MODEE, int CVTOUT>
__global__ __launch_bounds__(128) void k_hmma(
    const __half* __restrict__ ah, const __half* __restrict__ gh,
    const int* __restrict__ idx,
    const __half* __restrict__ wth, const __half* __restrict__ wtl,
    const float* __restrict__ bias,
    float* __restrict__ C, __half* __restrict__ Ch,
    int M, int Nf)
{
    constexpr int K = KCHUNKS * 32;
    constexpr int STG = 30720;
    constexpr int AOFF = 0, BHOFF = 10240, BLOFF = 20480;
    constexpr int IDX_OFF = 3 * STG;

    extern __shared__ char sm[];
    int* sIdx = (int*)(sm + IDX_OFF);
    uint32_t smb = smem_u32(sm);

    int t = threadIdx.x;
    int lane = t & 31;
    int w = t >> 5;
    int wm = w & 1, wn = w >> 1;
    int p0 = blockIdx.x * 128;
    int f0 = blockIdx.y * 128;

    if (MODEB == 1 || MODEE == 1) {
        if (t < 128) sIdx[t] = (p0 + t < M) ? idx[p0 + t] : 0;
        __syncthreads();
    }

    auto fill = [&](int s, int c) {
        int k0 = c * 32;
        uint32_t base = smb + s * STG;
        // A tile: 512 x 16B
#pragma unroll
        for (int it = 0; it < 4; it++) {
            int e = t + it * 128;
            int row = e >> 2, q = e & 3;
            int gp = p0 + row;
            const __half* srcp;
            if (MODEB == 0) {
                srcp = ah + (size_t)gp * K + k0 + q * 8;
            } else {
                if (k0 < 128) srcp = gh + (size_t)sIdx[row] * 128 + k0 + q * 8;
                else          srcp = ah + (size_t)gp * 128 + (k0 - 128) + q * 8;
            }
            cp16(base + AOFF + row * 80 + q * 16, srcp, gp < M);
        }
        // B hi/lo tiles: 1024 x 16B
#pragma unroll
        for (int it = 0; it < 8; it++) {
            int e = t + it * 128;
            int hl = e >> 9;
            int n = (e >> 2) & 127;
            int q = e & 3;
            const __half* srcp = (hl ? wtl : wth) + (size_t)(f0 + n) * K + k0 + q * 8;
            cp16(base + (hl ? BLOFF : BHOFF) + n * 80 + q * 16, srcp, true);
        }
        cp_commit();
    };

    float acc[4][8][4];
#pragma unroll
    for (int i = 0; i < 4; i++)
#pragma unroll
        for (int j = 0; j < 8; j++)
#pragma unroll
            for (int r = 0; r < 4; r++) acc[i][j][r] = 0.f;

    int ar  = ((lane >> 3) & 1) * 8 + (lane & 7);
    int akb = (lane >> 4) * 16;
    int bn  = (lane >> 4) * 8 + (lane & 7);
    int bkb = ((lane >> 3) & 1) * 16;

    fill(0, 0);
    if (KCHUNKS > 1) fill(1, 1);

#pragma unroll 1
    for (int c = 0; c < KCHUNKS; c++) {
        if (c + 1 < KCHUNKS) cp_wait1(); else cp_wait0();
        __syncthreads();
        if (c + 2 < KCHUNKS) fill((c + 2) % 3, c + 2);
        uint32_t base = smb + (c % 3) * STG;
#pragma unroll
        for (int ks = 0; ks < 2; ks++) {
            int kb = ks * 32;
            uint32_t a[4][4], bh[4][4], bx[4][4];
#pragma unroll
            for (int i = 0; i < 4; i++)
                ldmx4(a[i], base + AOFF + (uint32_t)(wm * 64 + i * 16 + ar) * 80 + kb + akb);
#pragma unroll
            for (int j2 = 0; j2 < 4; j2++)
                ldmx4(bh[j2], base + BHOFF + (uint32_t)(wn * 64 + j2 * 16 + bn) * 80 + kb + bkb);
#pragma unroll
            for (int i = 0; i < 4; i++)
#pragma unroll
                for (int j = 0; j < 8; j++)
                    mma16816(acc[i][j], a[i], bh[j >> 1][(j & 1) * 2], bh[j >> 1][(j & 1) * 2 + 1]);
#pragma unroll
            for (int j2 = 0; j2 < 4; j2++)
                ldmx4(bx[j2], base + BLOFF + (uint32_t)(wn * 64 + j2 * 16 + bn) * 80 + kb + bkb);
#pragma unroll
            for (int i = 0; i < 4; i++)
#pragma unroll
                for (int j = 0; j < 8; j++)
                    mma16816(acc[i][j], a[i], bx[j >> 1][(j & 1) * 2], bx[j >> 1][(j & 1) * 2 + 1]);
        }
        __syncthreads();
    }

    // ---- epilogue ----
#pragma unroll
    for (int i = 0; i < 4; i++) {
        int pa = p0 + wm * 64 + i * 16 + (lane >> 2);
        int pb = pa + 8;
#pragma unroll
        for (int j = 0; j < 8; j++) {
            int f = f0 + wn * 64 + j * 8 + (lane & 3) * 2;
            float2 bj = *(const float2*)(bias + f);
            float v0 = fmaxf(acc[i][j][0] + bj.x, 0.f);
            float v1 = fmaxf(acc[i][j][1] + bj.y, 0.f);
            float v2 = fmaxf(acc[i][j][2] + bj.x, 0.f);
            float v3 = fmaxf(acc[i][j][3] + bj.y, 0.f);
            if (MODEE == 0) {
                if (CVTOUT) {
                    if (pa < M) *(uint32_t*)(Ch + (size_t)pa * Nf + f) = packh2(v0, v1);
                    if (pb < M) *(uint32_t*)(Ch + (size_t)pb * Nf + f) = packh2(v2, v3);
                } else {
                    if (pa < M) *(float2*)(C + (size_t)pa * Nf + f) = make_float2(v0, v1);
                    if (pb < M) *(float2*)(C + (size_t)pb * Nf + f) = make_float2(v2, v3);
                }
            } else {
                if (pa < M) {
                    int* d = (int*)(C + (size_t)sIdx[pa - p0] * 256 + f);
                    atomicMax(d,     __float_as_int(v0));
                    atomicMax(d + 1, __float_as_int(v1));
                }
                if (pb < M) {
                    int* d = (int*)(C + (size_t)sIdx[pb - p0] * 256 + f);
                    atomicMax(d,     __float_as_int(v2));
                    atomicMax(d + 1, __float_as_int(v3));
                }
            }
        }
    }
}

// ---------------------------------------------------------------------------
extern "C" void kernel_launch(void* const* d_in, const int* in_sizes, int n_in,
                              void* d_out, int out_size)
{
    const float* inp = (const float*)d_in[0];
    const int*   idx = (const int*)d_in[1];   // int32 (JAX x64 disabled)
    const float* W1  = (const float*)d_in[2];
    const float* b1  = (const float*)d_in[3];
    const float* W2  = (const float*)d_in[4];
    const float* b2  = (const float*)d_in[5];
    const float* Wv1 = (const float*)d_in[6];
    const float* bv1 = (const float*)d_in[7];
    const float* W3  = (const float*)d_in[8];
    const float* b3  = (const float*)d_in[9];
    const float* W4  = (const float*)d_in[10];
    const float* b4  = (const float*)d_in[11];
    const float* Wv2 = (const float*)d_in[12];
    const float* bv2 = (const float*)d_in[13];
    float* out = (float*)d_out;

    float *vox1, *vox2;
    __half *pf2h, *vox1h, *vgh, *pf4h, *vox2h, *wth, *wtl;
    cudaGetSymbolAddress((void**)&vox1,  g_vox1);
    cudaGetSymbolAddress((void**)&vox2,  g_vox2);
    cudaGetSymbolAddress((void**)&pf2h,  g_pf2h);
    cudaGetSymbolAddress((void**)&vox1h, g_vox1h);
    cudaGetSymbolAddress((void**)&vgh,   g_vgh);
    cudaGetSymbolAddress((void**)&pf4h,  g_pf4h);
    cudaGetSymbolAddress((void**)&vox2h, g_vox2h);
    cudaGetSymbolAddress((void**)&wth,   g_wth);
    cudaGetSymbolAddress((void**)&wtl,   g_wtl);

    const int SMEM = 3 * 30720 + 512;
    cudaFuncSetAttribute(k_hmma<4,0,0,1>, cudaFuncAttributeMaxDynamicSharedMemorySize, SMEM);
    cudaFuncSetAttribute(k_hmma<8,1,0,1>, cudaFuncAttributeMaxDynamicSharedMemorySize, SMEM);
    cudaFuncSetAttribute(k_hmma<8,0,1,0>, cudaFuncAttributeMaxDynamicSharedMemorySize, SMEM);
    cudaFuncSetAttribute(k_hmma<8,0,0,0>, cudaFuncAttributeMaxDynamicSharedMemorySize, SMEM);

    // 0) zero accumulators, prep weights
    k_zero<<<2048, 256>>>();
    k_prep<<<(212992 + 255) / 256, 256>>>(Wv1, W3, W4, Wv2);

    // 1) point MLP -> pf2 fp16 + atomic max into vox1
    k1_pointwise<<<(NPTS + 255) / 256, 256>>>(inp, idx, W1, b1, W2, b2);

    // 1b) vox1 fp32 -> fp16
    k_cvt<<<(NVOX * 128 / 4 + 255) / 256, 256>>>(vox1, vox1h, NVOX * 128 / 4);

    // 2) vg = relu(vox1 @ Wv1 + bv1) -> fp16
    k_hmma<4,0,0,1><<<dim3(NVOX / 128, 1), 128, SMEM>>>(
        vox1h, nullptr, nullptr, wth + 0, wtl + 0, bv1, nullptr, vgh, NVOX, 128);
    // 3) pf4 = relu(concat(vg[idx], pf2) @ W3 + b3) -> fp16
    k_hmma<8,1,0,1><<<dim3((NPTS + 127) / 128, 2), 128, SMEM>>>(
        pf2h, vgh, idx, wth + 16384, wtl + 16384, b3, nullptr, pf4h, NPTS, 256);
    // 4) pf5 = relu(pf4 @ W4 + b4) -> atomicMax into vox2 (fp32)
    k_hmma<8,0,1,0><<<dim3((NPTS + 127) / 128, 2), 128, SMEM>>>(
        pf4h, nullptr, idx, wth + 81920, wtl + 81920, b4, vox2, nullptr, NPTS, 256);
    // 4b) vox2 fp32 -> fp16
    k_cvt<<<(NVOX * 256 / 4 + 255) / 256, 256>>>(vox2, vox2h, NVOX * 256 / 4);
    // 5) out = relu(vox2 @ Wv2 + bv2) (fp32 store)
    k_hmma<8,0,0,0><<<dim3(NVOX / 128, 2), 128, SMEM>>>(
        vox2h, nullptr, nullptr, wth + 147456, wtl + 147456, bv2, out, nullptr, NVOX, 256);
}

// round 8
// speedup vs baseline: 3.6013x; 1.2782x over previous
#include <cuda_runtime.h>
#include <cuda_fp16.h>
#include <cstdint>

#define NPTS 500000
#define NVOX 65536

// fp32 accumulators for atomic segment-max
static __device__ __align__(16) float g_vox1[(size_t)NVOX * 128];
static __device__ __align__(16) float g_vox2[(size_t)NVOX * 256];
// fp16 activation mirrors
static __device__ __align__(16) __half g_pf2h [(size_t)NPTS * 128];
static __device__ __align__(16) __half g_vox1h[(size_t)NVOX * 128];
static __device__ __align__(16) __half g_vgh  [(size_t)NVOX * 128];
static __device__ __align__(16) __half g_pf4h [(size_t)NPTS * 256];
static __device__ __align__(16) __half g_vox2h[(size_t)NVOX * 256];
// Pre-transposed fp16 weights: [Wv1t 128x128][W3t 256x256][W4t][Wv2t]
static __device__ __align__(16) __half g_wth[212992];

__device__ __forceinline__ uint32_t smem_u32(const void* p) {
    return (uint32_t)__cvta_generic_to_shared((void*)p);
}
__device__ __forceinline__ uint32_t packh2(float a, float b) {
    __half2 p = __floats2half2_rn(a, b);
    return *reinterpret_cast<uint32_t*>(&p);
}
__device__ __forceinline__ void ldmx4(uint32_t* r, uint32_t addr) {
    asm volatile("ldmatrix.sync.aligned.m8n8.x4.shared.b16 {%0,%1,%2,%3}, [%4];"
                 : "=r"(r[0]), "=r"(r[1]), "=r"(r[2]), "=r"(r[3]) : "r"(addr));
}
__device__ __forceinline__ void mma16816(float* d, const uint32_t* a, uint32_t b0, uint32_t b1) {
    asm volatile(
        "mma.sync.aligned.m16n8k16.row.col.f32.f16.f16.f32 "
        "{%0,%1,%2,%3}, {%4,%5,%6,%7}, {%8,%9}, {%0,%1,%2,%3};"
        : "+f"(d[0]), "+f"(d[1]), "+f"(d[2]), "+f"(d[3])
        : "r"(a[0]), "r"(a[1]), "r"(a[2]), "r"(a[3]), "r"(b0), "r"(b1));
}
__device__ __forceinline__ void cp16(uint32_t dst, const void* src, bool pred) {
    int sz = pred ? 16 : 0;
    asm volatile("cp.async.cg.shared.global [%0], [%1], 16, %2;"
                 :: "r"(dst), "l"(src), "r"(sz));
}
__device__ __forceinline__ void cp_commit() { asm volatile("cp.async.commit_group;"); }
__device__ __forceinline__ void cp_wait0()  { asm volatile("cp.async.wait_group 0;" ::: "memory"); }
__device__ __forceinline__ void cp_wait1()  { asm volatile("cp.async.wait_group 1;" ::: "memory"); }

// ---------------------------------------------------------------------------
__global__ void k_zero() {
    const size_t n4a = (size_t)NVOX * 128 / 4;
    const size_t n4b = (size_t)NVOX * 256 / 4;
    float4 z = make_float4(0.f, 0.f, 0.f, 0.f);
    size_t stride = (size_t)gridDim.x * blockDim.x;
    for (size_t j = (size_t)blockIdx.x * blockDim.x + threadIdx.x; j < n4a + n4b; j += stride) {
        if (j < n4a) ((float4*)g_vox1)[j] = z;
        else         ((float4*)g_vox2)[j - n4a] = z;
    }
}

// fp32 -> fp16, vectorized by 4
__global__ void k_cvt(const float* __restrict__ src, __half* __restrict__ dh, int n4) {
    int i = blockIdx.x * 256 + threadIdx.x;
    if (i >= n4) return;
    float4 v = ((const float4*)src)[i];
    *(uint2*)(dh + (size_t)i * 4) = make_uint2(packh2(v.x, v.y), packh2(v.z, v.w));
}

// Weight prep: W[K,Nf] fp32 -> Wt[Nf,K] fp16 (transposed)
__global__ void k_prep(const float* __restrict__ Wv1, const float* __restrict__ W3,
                       const float* __restrict__ W4,  const float* __restrict__ Wv2) {
    int i = blockIdx.x * 256 + threadIdx.x;
    if (i >= 212992) return;
    const float* W; int K, Nf, j = i;
    if (i < 16384)       { W = Wv1; K = 128; Nf = 128; }
    else if (i < 81920)  { W = W3;  K = 256; Nf = 256; j = i - 16384; }
    else if (i < 147456) { W = W4;  K = 256; Nf = 256; j = i - 81920; }
    else                 { W = Wv2; K = 256; Nf = 256; j = i - 147456; }
    int n = j / K, k = j - n * K;
    g_wth[i] = __float2half_rn(W[(size_t)k * Nf + n]);
}

// ---------------------------------------------------------------------------
// K1: per-point MLP 6 -> 64 -> 128, write pf2 fp16, atomicMax into vox1
// ---------------------------------------------------------------------------
__global__ __launch_bounds__(256) void k1_pointwise(
    const float* __restrict__ inp, const int* __restrict__ idx,
    const float* __restrict__ W1, const float* __restrict__ b1,
    const float* __restrict__ W2, const float* __restrict__ b2)
{
    __shared__ __align__(16) float sW1[6 * 64];
    __shared__ __align__(16) float sb1[64];
    __shared__ __align__(16) float sW2[64 * 128];
    __shared__ __align__(16) float sb2[128];
    int t = threadIdx.x;
    for (int i = t; i < 6 * 64; i += 256) sW1[i] = W1[i];
    if (t < 64)  sb1[t] = b1[t];
    for (int i = t; i < 64 * 128; i += 256) sW2[i] = W2[i];
    if (t < 128) sb2[t] = b2[t];
    __syncthreads();

    int i = blockIdx.x * 256 + t;
    if (i >= NPTS) return;

    float x[6];
#pragma unroll
    for (int c = 0; c < 6; c++) x[c] = inp[(size_t)i * 6 + c];

    float pf1[64];
#pragma unroll
    for (int j = 0; j < 64; j++) {
        float a = sb1[j];
#pragma unroll
        for (int c = 0; c < 6; c++) a = fmaf(x[c], sW1[c * 64 + j], a);
        pf1[j] = fmaxf(a, 0.f);
    }

    int v = idx[i];
    int* voxrow = (int*)(g_vox1 + (size_t)v * 128);
    const float4* sW2v = (const float4*)sW2;
    const float4* sb2v = (const float4*)sb2;

#pragma unroll 1
    for (int j4 = 0; j4 < 32; j4++) {
        float4 acc = sb2v[j4];
#pragma unroll
        for (int k = 0; k < 64; k++) {
            float4 w = sW2v[k * 32 + j4];
            float p = pf1[k];
            acc.x = fmaf(p, w.x, acc.x);
            acc.y = fmaf(p, w.y, acc.y);
            acc.z = fmaf(p, w.z, acc.z);
            acc.w = fmaf(p, w.w, acc.w);
        }
        acc.x = fmaxf(acc.x, 0.f); acc.y = fmaxf(acc.y, 0.f);
        acc.z = fmaxf(acc.z, 0.f); acc.w = fmaxf(acc.w, 0.f);
        *(uint2*)(g_pf2h + (size_t)i * 128 + j4 * 4) =
            make_uint2(packh2(acc.x, acc.y), packh2(acc.z, acc.w));
        atomicMax(voxrow + j4 * 4 + 0, __float_as_int(acc.x));
        atomicMax(voxrow + j4 * 4 + 1, __float_as_int(acc.y));
        atomicMax(voxrow + j4 * 4 + 2, __float_as_int(acc.z));
        atomicMax(voxrow + j4 * 4 + 3, __float_as_int(acc.w));
    }
}

// ---------------------------------------------------------------------------
// HMMA GEMM, fp16 single-pass: C[p,f] = relu( A[p,:] . Wt[f,:] + bias[f] )
// Block 128x128, K-chunk 32, 4 warps (64x64 warp tile), 3-stage cp.async.
//   MODEB 0: A rows from ah[p*K + k]
//   MODEB 1: k<128 from gh[idx[p]*128+k], else ah[p*128 + (k-128)]
//   MODEE 0: store (CVTOUT ? fp16 Ch : fp32 C)
//   MODEE 1: atomicMax into C[idx[p]*256 + f]
// Stage layout: A[128x80B] @0, B @10240  (stage = 20480B)
// ---------------------------------------------------------------------------
template <int KCHUNKS, int MODEB, int MODEE, int CVTOUT>
__global__ __launch_bounds__(128) void k_hmma(
    const __half* __restrict__ ah, const __half* __restrict__ gh,
    const int* __restrict__ idx,
    const __half* __restrict__ wth,
    const float* __restrict__ bias,
    float* __restrict__ C, __half* __restrict__ Ch,
    int M, int Nf)
{
    constexpr int K = KCHUNKS * 32;
    constexpr int STG = 20480;
    constexpr int AOFF = 0, BOFF = 10240;
    constexpr int IDX_OFF = 3 * STG;

    extern __shared__ char sm[];
    int* sIdx = (int*)(sm + IDX_OFF);
    uint32_t smb = smem_u32(sm);

    int t = threadIdx.x;
    int lane = t & 31;
    int w = t >> 5;
    int wm = w & 1, wn = w >> 1;
    int p0 = blockIdx.x * 128;
    int f0 = blockIdx.y * 128;

    if (MODEB == 1 || MODEE == 1) {
        if (t < 128) sIdx[t] = (p0 + t < M) ? idx[p0 + t] : 0;
        __syncthreads();
    }

    auto fill = [&](int s, int c) {
        int k0 = c * 32;
        uint32_t base = smb + s * STG;
        // A tile: 512 x 16B
#pragma unroll
        for (int it = 0; it < 4; it++) {
            int e = t + it * 128;
            int row = e >> 2, q = e & 3;
            int gp = p0 + row;
            const __half* srcp;
            if (MODEB == 0) {
                srcp = ah + (size_t)gp * K + k0 + q * 8;
            } else {
                if (k0 < 128) srcp = gh + (size_t)sIdx[row] * 128 + k0 + q * 8;
                else          srcp = ah + (size_t)gp * 128 + (k0 - 128) + q * 8;
            }
            cp16(base + AOFF + row * 80 + q * 16, srcp, gp < M);
        }
        // B tile: 512 x 16B
#pragma unroll
        for (int it = 0; it < 4; it++) {
            int e = t + it * 128;
            int n = e >> 2, q = e & 3;
            const __half* srcp = wth + (size_t)(f0 + n) * K + k0 + q * 8;
            cp16(base + BOFF + n * 80 + q * 16, srcp, true);
        }
        cp_commit();
    };

    float acc[4][8][4];
#pragma unroll
    for (int i = 0; i < 4; i++)
#pragma unroll
        for (int j = 0; j < 8; j++)
#pragma unroll
            for (int r = 0; r < 4; r++) acc[i][j][r] = 0.f;

    int ar  = ((lane >> 3) & 1) * 8 + (lane & 7);
    int akb = (lane >> 4) * 16;
    int bn  = (lane >> 4) * 8 + (lane & 7);
    int bkb = ((lane >> 3) & 1) * 16;

    fill(0, 0);
    if (KCHUNKS > 1) fill(1, 1);

#pragma unroll 1
    for (int c = 0; c < KCHUNKS; c++) {
        if (c + 1 < KCHUNKS) cp_wait1(); else cp_wait0();
        __syncthreads();
        if (c + 2 < KCHUNKS) fill((c + 2) % 3, c + 2);
        uint32_t base = smb + (c % 3) * STG;
#pragma unroll
        for (int ks = 0; ks < 2; ks++) {
            int kb = ks * 32;
            uint32_t a[4][4], bh[4][4];
#pragma unroll
            for (int i = 0; i < 4; i++)
                ldmx4(a[i], base + AOFF + (uint32_t)(wm * 64 + i * 16 + ar) * 80 + kb + akb);
#pragma unroll
            for (int j2 = 0; j2 < 4; j2++)
                ldmx4(bh[j2], base + BOFF + (uint32_t)(wn * 64 + j2 * 16 + bn) * 80 + kb + bkb);
#pragma unroll
            for (int i = 0; i < 4; i++)
#pragma unroll
                for (int j = 0; j < 8; j++)
                    mma16816(acc[i][j], a[i], bh[j >> 1][(j & 1) * 2], bh[j >> 1][(j & 1) * 2 + 1]);
        }
        __syncthreads();
    }

    // ---- epilogue ----
#pragma unroll
    for (int i = 0; i < 4; i++) {
        int pa = p0 + wm * 64 + i * 16 + (lane >> 2);
        int pb = pa + 8;
#pragma unroll
        for (int j = 0; j < 8; j++) {
            int f = f0 + wn * 64 + j * 8 + (lane & 3) * 2;
            float2 bj = *(const float2*)(bias + f);
            float v0 = fmaxf(acc[i][j][0] + bj.x, 0.f);
            float v1 = fmaxf(acc[i][j][1] + bj.y, 0.f);
            float v2 = fmaxf(acc[i][j][2] + bj.x, 0.f);
            float v3 = fmaxf(acc[i][j][3] + bj.y, 0.f);
            if (MODEE == 0) {
                if (CVTOUT) {
                    if (pa < M) *(uint32_t*)(Ch + (size_t)pa * Nf + f) = packh2(v0, v1);
                    if (pb < M) *(uint32_t*)(Ch + (size_t)pb * Nf + f) = packh2(v2, v3);
                } else {
                    if (pa < M) *(float2*)(C + (size_t)pa * Nf + f) = make_float2(v0, v1);
                    if (pb < M) *(float2*)(C + (size_t)pb * Nf + f) = make_float2(v2, v3);
                }
            } else {
                if (pa < M) {
                    int* d = (int*)(C + (size_t)sIdx[pa - p0] * 256 + f);
                    atomicMax(d,     __float_as_int(v0));
                    atomicMax(d + 1, __float_as_int(v1));
                }
                if (pb < M) {
                    int* d = (int*)(C + (size_t)sIdx[pb - p0] * 256 + f);
                    atomicMax(d,     __float_as_int(v2));
                    atomicMax(d + 1, __float_as_int(v3));
                }
            }
        }
    }
}

// ---------------------------------------------------------------------------
extern "C" void kernel_launch(void* const* d_in, const int* in_sizes, int n_in,
                              void* d_out, int out_size)
{
    const float* inp = (const float*)d_in[0];
    const int*   idx = (const int*)d_in[1];   // int32 (JAX x64 disabled)
    const float* W1  = (const float*)d_in[2];
    const float* b1  = (const float*)d_in[3];
    const float* W2  = (const float*)d_in[4];
    const float* b2  = (const float*)d_in[5];
    const float* Wv1 = (const float*)d_in[6];
    const float* bv1 = (const float*)d_in[7];
    const float* W3  = (const float*)d_in[8];
    const float* b3  = (const float*)d_in[9];
    const float* W4  = (const float*)d_in[10];
    const float* b4  = (const float*)d_in[11];
    const float* Wv2 = (const float*)d_in[12];
    const float* bv2 = (const float*)d_in[13];
    float* out = (float*)d_out;

    float *vox1, *vox2;
    __half *pf2h, *vox1h, *vgh, *pf4h, *vox2h, *wth;
    cudaGetSymbolAddress((void**)&vox1,  g_vox1);
    cudaGetSymbolAddress((void**)&vox2,  g_vox2);
    cudaGetSymbolAddress((void**)&pf2h,  g_pf2h);
    cudaGetSymbolAddress((void**)&vox1h, g_vox1h);
    cudaGetSymbolAddress((void**)&vgh,   g_vgh);
    cudaGetSymbolAddress((void**)&pf4h,  g_pf4h);
    cudaGetSymbolAddress((void**)&vox2h, g_vox2h);
    cudaGetSymbolAddress((void**)&wth,   g_wth);

    const int SMEM = 3 * 20480 + 512;
    cudaFuncSetAttribute(k_hmma<4,0,0,1>, cudaFuncAttributeMaxDynamicSharedMemorySize, SMEM);
    cudaFuncSetAttribute(k_hmma<8,1,0,1>, cudaFuncAttributeMaxDynamicSharedMemorySize, SMEM);
    cudaFuncSetAttribute(k_hmma<8,0,1,0>, cudaFuncAttributeMaxDynamicSharedMemorySize, SMEM);
    cudaFuncSetAttribute(k_hmma<8,0,0,0>, cudaFuncAttributeMaxDynamicSharedMemorySize, SMEM);

    // 0) zero accumulators, prep weights
    k_zero<<<2048, 256>>>();
    k_prep<<<(212992 + 255) / 256, 256>>>(Wv1, W3, W4, Wv2);

    // 1) point MLP -> pf2 fp16 + atomic max into vox1
    k1_pointwise<<<(NPTS + 255) / 256, 256>>>(inp, idx, W1, b1, W2, b2);

    // 1b) vox1 fp32 -> fp16
    k_cvt<<<(NVOX * 128 / 4 + 255) / 256, 256>>>(vox1, vox1h, NVOX * 128 / 4);

    // 2) vg = relu(vox1 @ Wv1 + bv1) -> fp16
    k_hmma<4,0,0,1><<<dim3(NVOX / 128, 1), 128, SMEM>>>(
        vox1h, nullptr, nullptr, wth + 0, bv1, nullptr, vgh, NVOX, 128);
    // 3) pf4 = relu(concat(vg[idx], pf2) @ W3 + b3) -> fp16
    k_hmma<8,1,0,1><<<dim3((NPTS + 127) / 128, 2), 128, SMEM>>>(
        pf2h, vgh, idx, wth + 16384, b3, nullptr, pf4h, NPTS, 256);
    // 4) pf5 = relu(pf4 @ W4 + b4) -> atomicMax into vox2 (fp32)
    k_hmma<8,0,1,0><<<dim3((NPTS + 127) / 128, 2), 128, SMEM>>>(
        pf4h, nullptr, idx, wth + 81920, b4, vox2, nullptr, NPTS, 256);
    // 4b) vox2 fp32 -> fp16
    k_cvt<<<(NVOX * 256 / 4 + 255) / 256, 256>>>(vox2, vox2h, NVOX * 256 / 4);
    // 5) out = relu(vox2 @ Wv2 + bv2) (fp32 store)
    k_hmma<8,0,0,0><<<dim3(NVOX / 128, 2), 128, SMEM>>>(
        vox2h, nullptr, nullptr, wth + 147456, bv2, out, nullptr, NVOX, 256);
}

// round 10
// speedup vs baseline: 5.1694x; 1.4354x over previous
#include <cuda_runtime.h>
#include <cuda_fp16.h>
#include <cstdint>

#define NPTS 500000
#define NVOX 65536

// fp32 accumulators for atomic segment-max
static __device__ __align__(16) float g_vox1[(size_t)NVOX * 128];
static __device__ __align__(16) float g_vox2[(size_t)NVOX * 256];
// fp16 activation mirrors
static __device__ __align__(16) __half g_pf1h [(size_t)NPTS * 64];
static __device__ __align__(16) __half g_pf2h [(size_t)NPTS * 128];
static __device__ __align__(16) __half g_vox1h[(size_t)NVOX * 128];
static __device__ __align__(16) __half g_vgh  [(size_t)NVOX * 128];
static __device__ __align__(16) __half g_pf4h [(size_t)NPTS * 256];
static __device__ __align__(16) __half g_vox2h[(size_t)NVOX * 256];
// Pre-transposed fp16 weights: [Wv1t 128x128][W3t 256x256][W4t][Wv2t][W2t 128x64]
static __device__ __align__(16) __half g_wth[221184];

__device__ __forceinline__ uint32_t smem_u32(const void* p) {
    return (uint32_t)__cvta_generic_to_shared((void*)p);
}
__device__ __forceinline__ uint32_t packh2(float a, float b) {
    __half2 p = __floats2half2_rn(a, b);
    return *reinterpret_cast<uint32_t*>(&p);
}
__device__ __forceinline__ void ldmx4(uint32_t* r, uint32_t addr) {
    asm volatile("ldmatrix.sync.aligned.m8n8.x4.shared.b16 {%0,%1,%2,%3}, [%4];"
                 : "=r"(r[0]), "=r"(r[1]), "=r"(r[2]), "=r"(r[3]) : "r"(addr));
}
__device__ __forceinline__ void mma16816(float* d, const uint32_t* a, uint32_t b0, uint32_t b1) {
    asm volatile(
        "mma.sync.aligned.m16n8k16.row.col.f32.f16.f16.f32 "
        "{%0,%1,%2,%3}, {%4,%5,%6,%7}, {%8,%9}, {%0,%1,%2,%3};"
        : "+f"(d[0]), "+f"(d[1]), "+f"(d[2]), "+f"(d[3])
        : "r"(a[0]), "r"(a[1]), "r"(a[2]), "r"(a[3]), "r"(b0), "r"(b1));
}
__device__ __forceinline__ void cp16(uint32_t dst, const void* src, bool pred) {
    int sz = pred ? 16 : 0;
    asm volatile("cp.async.cg.shared.global [%0], [%1], 16, %2;"
                 :: "r"(dst), "l"(src), "r"(sz));
}
__device__ __forceinline__ void cp_commit() { asm volatile("cp.async.commit_group;"); }
__device__ __forceinline__ void cp_wait0()  { asm volatile("cp.async.wait_group 0;" ::: "memory"); }
__device__ __forceinline__ void cp_wait1()  { asm volatile("cp.async.wait_group 1;" ::: "memory"); }

// ---------------------------------------------------------------------------
__global__ void k_zero() {
    const size_t n4a = (size_t)NVOX * 128 / 4;
    const size_t n4b = (size_t)NVOX * 256 / 4;
    float4 z = make_float4(0.f, 0.f, 0.f, 0.f);
    size_t stride = (size_t)gridDim.x * blockDim.x;
    for (size_t j = (size_t)blockIdx.x * blockDim.x + threadIdx.x; j < n4a + n4b; j += stride) {
        if (j < n4a) ((float4*)g_vox1)[j] = z;
        else         ((float4*)g_vox2)[j - n4a] = z;
    }
}

// fp32 -> fp16, vectorized by 4
__global__ void k_cvt(const float* __restrict__ src, __half* __restrict__ dh, int n4) {
    int i = blockIdx.x * 256 + threadIdx.x;
    if (i >= n4) return;
    float4 v = ((const float4*)src)[i];
    *(uint2*)(dh + (size_t)i * 4) = make_uint2(packh2(v.x, v.y), packh2(v.z, v.w));
}

// Weight prep: W[K,Nf] fp32 -> Wt[Nf,K] fp16 (transposed)
__global__ void k_prep(const float* __restrict__ Wv1, const float* __restrict__ W3,
                       const float* __restrict__ W4,  const float* __restrict__ Wv2,
                       const float* __restrict__ W2) {
    int i = blockIdx.x * 256 + threadIdx.x;
    if (i >= 221184) return;
    const float* W; int K, Nf, j = i;
    if (i < 16384)       { W = Wv1; K = 128; Nf = 128; }
    else if (i < 81920)  { W = W3;  K = 256; Nf = 256; j = i - 16384; }
    else if (i < 147456) { W = W4;  K = 256; Nf = 256; j = i - 81920; }
    else if (i < 212992) { W = Wv2; K = 256; Nf = 256; j = i - 147456; }
    else                 { W = W2;  K = 64;  Nf = 128; j = i - 212992; }
    int n = j / K, k = j - n * K;
    g_wth[i] = __float2half_rn(W[(size_t)k * Nf + n]);
}

// ---------------------------------------------------------------------------
// K1a: per-point MLP 6 -> 64, write pf1 fp16 (full 64 outputs = 8 x uint4)
// ---------------------------------------------------------------------------
__global__ __launch_bounds__(256) void k1a_pointwise(
    const float* __restrict__ inp,
    const float* __restrict__ W1, const float* __restrict__ b1)
{
    __shared__ __align__(16) float sW1[6 * 64];
    __shared__ __align__(16) float sb1[64];
    int t = threadIdx.x;
    for (int i = t; i < 6 * 64; i += 256) sW1[i] = W1[i];
    if (t < 64) sb1[t] = b1[t];
    __syncthreads();

    int i = blockIdx.x * 256 + t;
    if (i >= NPTS) return;

    float x[6];
#pragma unroll
    for (int c = 0; c < 6; c++) x[c] = inp[(size_t)i * 6 + c];

    uint32_t outv[32];                     // 32 x half2 = 64 halves
#pragma unroll
    for (int j2 = 0; j2 < 32; j2++) {
        float a0 = sb1[j2 * 2], a1 = sb1[j2 * 2 + 1];
#pragma unroll
        for (int c = 0; c < 6; c++) {
            a0 = fmaf(x[c], sW1[c * 64 + j2 * 2], a0);
            a1 = fmaf(x[c], sW1[c * 64 + j2 * 2 + 1], a1);
        }
        outv[j2] = packh2(fmaxf(a0, 0.f), fmaxf(a1, 0.f));
    }
    uint4* dst = (uint4*)(g_pf1h + (size_t)i * 64);
#pragma unroll
    for (int q = 0; q < 8; q++) dst[q] = ((uint4*)outv)[q];
}

// ---------------------------------------------------------------------------
// HMMA GEMM, fp16: C[p,f] = relu( A[p,:] . Wt[f,:] + bias[f] )
// Block 128x128, K-chunk 32, 4 warps (64x64 warp tile), 3-stage cp.async.
//   MODEB 0: A rows from ah[p*K + k]
//   MODEB 1: k<128 from gh[idx[p]*128+k], else ah[p*128 + (k-128)]
//   MODEE 0: store (CVTOUT ? fp16 Ch : fp32 C)
//   MODEE 1: atomicMax into C[idx[p]*Nf + f]
//   MODEE 2: fp16 store to Ch[p*Nf+f] AND atomicMax into C[idx[p]*Nf + f]
// Stage layout: A[128x80B] @0, B @10240  (stage = 20480B)
// ---------------------------------------------------------------------------
template <int KCHUNKS, int MODEB, int MODEE, int CVTOUT>
__global__ __launch_bounds__(128) void k_hmma(
    const __half* __restrict__ ah, const __half* __restrict__ gh,
    const int* __restrict__ idx,
    const __half* __restrict__ wth,
    const float* __restrict__ bias,
    float* __restrict__ C, __half* __restrict__ Ch,
    int M, int Nf)
{
    constexpr int K = KCHUNKS * 32;
    constexpr int STG = 20480;
    constexpr int AOFF = 0, BOFF = 10240;
    constexpr int IDX_OFF = 3 * STG;

    extern __shared__ char sm[];
    int* sIdx = (int*)(sm + IDX_OFF);
    uint32_t smb = smem_u32(sm);

    int t = threadIdx.x;
    int lane = t & 31;
    int w = t >> 5;
    int wm = w & 1, wn = w >> 1;
    int p0 = blockIdx.x * 128;
    int f0 = blockIdx.y * 128;

    if (MODEB == 1 || MODEE >= 1) {
        if (t < 128) sIdx[t] = (p0 + t < M) ? idx[p0 + t] : 0;
        __syncthreads();
    }

    auto fill = [&](int s, int c) {
        int k0 = c * 32;
        uint32_t base = smb + s * STG;
        // A tile: 512 x 16B
#pragma unroll
        for (int it = 0; it < 4; it++) {
            int e = t + it * 128;
            int row = e >> 2, q = e & 3;
            int gp = p0 + row;
            const __half* srcp;
            if (MODEB == 0) {
                srcp = ah + (size_t)gp * K + k0 + q * 8;
            } else {
                if (k0 < 128) srcp = gh + (size_t)sIdx[row] * 128 + k0 + q * 8;
                else          srcp = ah + (size_t)gp * 128 + (k0 - 128) + q * 8;
            }
            cp16(base + AOFF + row * 80 + q * 16, srcp, gp < M);
        }
        // B tile: 512 x 16B
#pragma unroll
        for (int it = 0; it < 4; it++) {
            int e = t + it * 128;
            int n = e >> 2, q = e & 3;
            const __half* srcp = wth + (size_t)(f0 + n) * K + k0 + q * 8;
            cp16(base + BOFF + n * 80 + q * 16, srcp, true);
        }
        cp_commit();
    };

    float acc[4][8][4];
#pragma unroll
    for (int i = 0; i < 4; i++)
#pragma unroll
        for (int j = 0; j < 8; j++)
#pragma unroll
            for (int r = 0; r < 4; r++) acc[i][j][r] = 0.f;

    int ar  = ((lane >> 3) & 1) * 8 + (lane & 7);
    int akb = (lane >> 4) * 16;
    int bn  = (lane >> 4) * 8 + (lane & 7);
    int bkb = ((lane >> 3) & 1) * 16;

    fill(0, 0);
    if (KCHUNKS > 1) fill(1, 1);

#pragma unroll 1
    for (int c = 0; c < KCHUNKS; c++) {
        if (c + 1 < KCHUNKS) cp_wait1(); else cp_wait0();
        __syncthreads();
        if (c + 2 < KCHUNKS) fill((c + 2) % 3, c + 2);
        uint32_t base = smb + (c % 3) * STG;
#pragma unroll
        for (int ks = 0; ks < 2; ks++) {
            int kb = ks * 32;
            uint32_t a[4][4], bh[4][4];
#pragma unroll
            for (int i = 0; i < 4; i++)
                ldmx4(a[i], base + AOFF + (uint32_t)(wm * 64 + i * 16 + ar) * 80 + kb + akb);
#pragma unroll
            for (int j2 = 0; j2 < 4; j2++)
                ldmx4(bh[j2], base + BOFF + (uint32_t)(wn * 64 + j2 * 16 + bn) * 80 + kb + bkb);
#pragma unroll
            for (int i = 0; i < 4; i++)
#pragma unroll
                for (int j = 0; j < 8; j++)
                    mma16816(acc[i][j], a[i], bh[j >> 1][(j & 1) * 2], bh[j >> 1][(j & 1) * 2 + 1]);
        }
        __syncthreads();
    }

    // ---- epilogue ----
#pragma unroll
    for (int i = 0; i < 4; i++) {
        int pa = p0 + wm * 64 + i * 16 + (lane >> 2);
        int pb = pa + 8;
#pragma unroll
        for (int j = 0; j < 8; j++) {
            int f = f0 + wn * 64 + j * 8 + (lane & 3) * 2;
            float2 bj = *(const float2*)(bias + f);
            float v0 = fmaxf(acc[i][j][0] + bj.x, 0.f);
            float v1 = fmaxf(acc[i][j][1] + bj.y, 0.f);
            float v2 = fmaxf(acc[i][j][2] + bj.x, 0.f);
            float v3 = fmaxf(acc[i][j][3] + bj.y, 0.f);
            if (MODEE == 0) {
                if (CVTOUT) {
                    if (pa < M) *(uint32_t*)(Ch + (size_t)pa * Nf + f) = packh2(v0, v1);
                    if (pb < M) *(uint32_t*)(Ch + (size_t)pb * Nf + f) = packh2(v2, v3);
                } else {
                    if (pa < M) *(float2*)(C + (size_t)pa * Nf + f) = make_float2(v0, v1);
                    if (pb < M) *(float2*)(C + (size_t)pb * Nf + f) = make_float2(v2, v3);
                }
            } else {
                if (pa < M) {
                    if (MODEE == 2) *(uint32_t*)(Ch + (size_t)pa * Nf + f) = packh2(v0, v1);
                    int* d = (int*)(C + (size_t)sIdx[pa - p0] * Nf + f);
                    atomicMax(d,     __float_as_int(v0));
                    atomicMax(d + 1, __float_as_int(v1));
                }
                if (pb < M) {
                    if (MODEE == 2) *(uint32_t*)(Ch + (size_t)pb * Nf + f) = packh2(v2, v3);
                    int* d = (int*)(C + (size_t)sIdx[pb - p0] * Nf + f);
                    atomicMax(d,     __float_as_int(v2));
                    atomicMax(d + 1, __float_as_int(v3));
                }
            }
        }
    }
}

// ---------------------------------------------------------------------------
extern "C" void kernel_launch(void* const* d_in, const int* in_sizes, int n_in,
                              void* d_out, int out_size)
{
    const float* inp = (const float*)d_in[0];
    const int*   idx = (const int*)d_in[1];   // int32 (JAX x64 disabled)
    const float* W1  = (const float*)d_in[2];
    const float* b1  = (const float*)d_in[3];
    const float* W2  = (const float*)d_in[4];
    const float* b2  = (const float*)d_in[5];
    const float* Wv1 = (const float*)d_in[6];
    const float* bv1 = (const float*)d_in[7];
    const float* W3  = (const float*)d_in[8];
    const float* b3  = (const float*)d_in[9];
    const float* W4  = (const float*)d_in[10];
    const float* b4  = (const float*)d_in[11];
    const float* Wv2 = (const float*)d_in[12];
    const float* bv2 = (const float*)d_in[13];
    float* out = (float*)d_out;

    float *vox1, *vox2;
    __half *pf1h, *pf2h, *vox1h, *vgh, *pf4h, *vox2h, *wth;
    cudaGetSymbolAddress((void**)&vox1,  g_vox1);
    cudaGetSymbolAddress((void**)&vox2,  g_vox2);
    cudaGetSymbolAddress((void**)&pf1h,  g_pf1h);
    cudaGetSymbolAddress((void**)&pf2h,  g_pf2h);
    cudaGetSymbolAddress((void**)&vox1h, g_vox1h);
    cudaGetSymbolAddress((void**)&vgh,   g_vgh);
    cudaGetSymbolAddress((void**)&pf4h,  g_pf4h);
    cudaGetSymbolAddress((void**)&vox2h, g_vox2h);
    cudaGetSymbolAddress((void**)&wth,   g_wth);

    const int SMEM = 3 * 20480 + 512;
    cudaFuncSetAttribute(k_hmma<2,0,2,1>, cudaFuncAttributeMaxDynamicSharedMemorySize, SMEM);
    cudaFuncSetAttribute(k_hmma<4,0,0,1>, cudaFuncAttributeMaxDynamicSharedMemorySize, SMEM);
    cudaFuncSetAttribute(k_hmma<8,1,0,1>, cudaFuncAttributeMaxDynamicSharedMemorySize, SMEM);
    cudaFuncSetAttribute(k_hmma<8,0,1,0>, cudaFuncAttributeMaxDynamicSharedMemorySize, SMEM);
    cudaFuncSetAttribute(k_hmma<8,0,0,0>, cudaFuncAttributeMaxDynamicSharedMemorySize, SMEM);

    // 0) zero accumulators, prep weights
    k_zero<<<2048, 256>>>();
    k_prep<<<(221184 + 255) / 256, 256>>>(Wv1, W3, W4, Wv2, W2);

    // 1a) point MLP 6->64 -> pf1 fp16
    k1a_pointwise<<<(NPTS + 255) / 256, 256>>>(inp, W1, b1);

    // 1b) pf2 = relu(pf1 @ W2 + b2): HMMA, fp16 store + atomicMax into vox1
    k_hmma<2,0,2,1><<<dim3((NPTS + 127) / 128, 1), 128, SMEM>>>(
        pf1h, nullptr, idx, wth + 212992, b2, vox1, pf2h, NPTS, 128);

    // 1c) vox1 fp32 -> fp16
    k_cvt<<<(NVOX * 128 / 4 + 255) / 256, 256>>>(vox1, vox1h, NVOX * 128 / 4);

    // 2) vg = relu(vox1 @ Wv1 + bv1) -> fp16
    k_hmma<4,0,0,1><<<dim3(NVOX / 128, 1), 128, SMEM>>>(
        vox1h, nullptr, nullptr, wth + 0, bv1, nullptr, vgh, NVOX, 128);
    // 3) pf4 = relu(concat(vg[idx], pf2) @ W3 + b3) -> fp16
    k_hmma<8,1,0,1><<<dim3((NPTS + 127) / 128, 2), 128, SMEM>>>(
        pf2h, vgh, idx, wth + 16384, b3, nullptr, pf4h, NPTS, 256);
    // 4) pf5 = relu(pf4 @ W4 + b4) -> atomicMax into vox2 (fp32)
    k_hmma<8,0,1,0><<<dim3((NPTS + 127) / 128, 2), 128, SMEM>>>(
        pf4h, nullptr, idx, wth + 81920, b4, vox2, nullptr, NPTS, 256);
    // 4b) vox2 fp32 -> fp16
    k_cvt<<<(NVOX * 256 / 4 + 255) / 256, 256>>>(vox2, vox2h, NVOX * 256 / 4);
    // 5) out = relu(vox2 @ Wv2 + bv2) (fp32 store)
    k_hmma<8,0,0,0><<<dim3(NVOX / 128, 2), 128, SMEM>>>(
        vox2h, nullptr, nullptr, wth + 147456, bv2, out, nullptr, NVOX, 256);
}